// round 10
// baseline (speedup 1.0000x reference)
#include <cuda_runtime.h>
#include <cuda_fp16.h>
#include <math.h>
#include <stdint.h>

#define HW 65536
#define PW 260

// ---------------- device scratch (allocation-free) ----------------
// Channel layout everywhere: q = o*16 + ci   (o = orientation, ci = base channel)
__device__ __align__(1024) __half g_actA[2*PW*PW*128];    // padded NHWC fp16 RAW (ping)
__device__ __align__(1024) __half g_actB[2*PW*PW*128];    // padded NHWC fp16 RAW (pong)
__device__ __align__(1024) __half g_wA[25*16384];         // gconv weights [tap][p][q] fp16
__device__ __align__(1024) __half g_wA4[16384];           // conv4 weights [p][q] fp16
__device__ float g_wrL[8*3*16*49];
__device__ float g_ps1[1024*128], g_ps2[1024*128];        // stats partials
__device__ float g_sc[16], g_bi[16];

// ---------------- PTX helpers (sm_80-era, portable to plain sm_103) ----------------
__device__ __forceinline__ uint32_t smem_u32(const void* p) {
    uint32_t a;
    asm("{ .reg .u64 t; cvta.to.shared.u64 t, %1; cvt.u32.u64 %0, t; }" : "=r"(a) : "l"(p));
    return a;
}
__device__ __forceinline__ void cp_async16(uint32_t s, const void* g) {
    asm volatile("cp.async.cg.shared.global [%0], [%1], 16;" :: "r"(s), "l"(g) : "memory");
}
__device__ __forceinline__ void ldm_x4(uint32_t* r, uint32_t a) {
    asm volatile("ldmatrix.sync.aligned.m8n8.x4.shared.b16 {%0,%1,%2,%3}, [%4];"
        : "=r"(r[0]), "=r"(r[1]), "=r"(r[2]), "=r"(r[3]) : "r"(a));
}
__device__ __forceinline__ void mma16816(float* d, const uint32_t* a, const uint32_t* b) {
    asm volatile("mma.sync.aligned.m16n8k16.row.col.f32.f16.f16.f32 "
        "{%0,%1,%2,%3}, {%4,%5,%6,%7}, {%8,%9}, {%0,%1,%2,%3};"
        : "+f"(d[0]), "+f"(d[1]), "+f"(d[2]), "+f"(d[3])
        : "r"(a[0]), "r"(a[1]), "r"(a[2]), "r"(a[3]), "r"(b[0]), "r"(b[1]));
}

// ---------------- bilinear kernel rotation ----------------
__device__ __forceinline__ float rot_sample(const float* W, int k, float cs, float sn, int i, int j) {
    float c  = 0.5f * (float)(k - 1);
    float ys = (float)i - c, xs = (float)j - c;
    float sy = cs * ys - sn * xs + c;
    float sx = sn * ys + cs * xs + c;
    float fy = floorf(sy), fx = floorf(sx);
    int y0 = (int)fy, x0 = (int)fx;
    float wy = sy - fy, wx = sx - fx;
    float v00 = (y0   >= 0 && y0   < k && x0   >= 0 && x0   < k) ? W[y0*k + x0]       : 0.f;
    float v01 = (y0   >= 0 && y0   < k && x0+1 >= 0 && x0+1 < k) ? W[y0*k + x0 + 1]   : 0.f;
    float v10 = (y0+1 >= 0 && y0+1 < k && x0   >= 0 && x0   < k) ? W[(y0+1)*k + x0]   : 0.f;
    float v11 = (y0+1 >= 0 && y0+1 < k && x0+1 >= 0 && x0+1 < k) ? W[(y0+1)*k + x0+1] : 0.f;
    return v00*(1.f-wy)*(1.f-wx) + v01*(1.f-wy)*wx + v10*wy*(1.f-wx) + v11*wy*wx;
}

__global__ void rotate_lift_kernel(const float* __restrict__ lw) {
    int idx = blockIdx.x * 256 + threadIdx.x;
    if (idx >= 8*3*16*49) return;
    int j  = idx % 49;
    int co = (idx / 49) % 16;
    int ci = (idx / (49*16)) % 3;
    int m  = idx / (49*48);
    float th = (float)m * 0.78539816339744831f;
    float cs = cosf(th), sn = sinf(th);
    const float* W = lw + (co*3 + ci) * 49;
    g_wrL[((m*3 + ci)*16 + co)*49 + j] = rot_sample(W, 7, cs, sn, j/7, j%7);
}

// pack gconv weights: A[tap][p=m*16+co][q=o*16+ci]
__global__ void pack_g_kernel(const float* __restrict__ w) {
    int idx = blockIdx.x * 256 + threadIdx.x;   // 409600 exact
    int tap = idx >> 14;
    int p = (idx >> 7) & 127, q = idx & 127;
    int m = p >> 4, co = p & 15, o = q >> 4, ci = q & 15;
    int oo = (o - m) & 7;
    float th = (float)m * 0.78539816339744831f;
    float cs = cosf(th), sn = sinf(th);
    float v = rot_sample(w + ((co*16 + ci)*8 + oo)*25, 5, cs, sn, tap/5, tap%5);
    g_wA[tap*16384 + p*128 + q] = __float2half(v);
}

__global__ void pack_w4_kernel(const float* __restrict__ w4) {
    int idx = blockIdx.x * 256 + threadIdx.x;   // 16384
    int p = idx >> 7, q = idx & 127;
    int m = p >> 4, co = p & 15, o = q >> 4, ci = q & 15;
    g_wA4[idx] = __float2half(w4[(co*16 + ci)*8 + ((o - m) & 7)]);
}

// ---------------- lift conv (scalar fp32) -> g_actA raw fp16 interior + BN0 partials ----------------
__global__ __launch_bounds__(256) void lift_kernel(const float* __restrict__ x) {
    int z = blockIdx.z; int b = z >> 3, m = z & 7;
    int x0 = blockIdx.x * 16, y0 = blockIdx.y * 16;
    int t = threadIdx.x; int tx = t & 15, ty = t >> 4;
    __shared__ float s_in[22*22];
    __shared__ float s_w[16*49];
    __shared__ float s_red[8][32];
    float acc[16];
#pragma unroll
    for (int i = 0; i < 16; ++i) acc[i] = 0.f;
#pragma unroll 1
    for (int ci = 0; ci < 3; ++ci) {
        const float* ip = x + (b*3 + ci) * HW;
        for (int idx = t; idx < 484; idx += 256) {
            int iy = idx / 22, ix = idx - iy*22;
            int gy = y0 + iy - 3; gy = gy < 0 ? -gy : (gy > 255 ? 510 - gy : gy);
            int gx = x0 + ix - 3; gx = gx < 0 ? -gx : (gx > 255 ? 510 - gx : gx);
            s_in[idx] = ip[gy*256 + gx];
        }
        const float* wp = g_wrL + (m*3 + ci) * 784;
        for (int idx = t; idx < 784; idx += 256) s_w[idx] = wp[idx];
        __syncthreads();
        float tap[49];
#pragma unroll
        for (int ky = 0; ky < 7; ++ky)
#pragma unroll
            for (int kx = 0; kx < 7; ++kx)
                tap[ky*7 + kx] = s_in[(ty+ky)*22 + tx + kx];
#pragma unroll
        for (int co = 0; co < 16; ++co) {
            float a = acc[co];
#pragma unroll
            for (int j = 0; j < 49; ++j) a = fmaf(tap[j], s_w[co*49 + j], a);
            acc[co] = a;
        }
        __syncthreads();
    }
    // ---- per-channel stats via warp butterfly (fp32 accumulators) ----
    int wid = t >> 5, ln = t & 31;
    {
        float sm[16], sq[16];
#pragma unroll
        for (int co = 0; co < 16; ++co) { sm[co] = acc[co]; sq[co] = acc[co]*acc[co]; }
#pragma unroll
        for (int off = 16; off > 0; off >>= 1)
#pragma unroll
            for (int co = 0; co < 16; ++co) {
                sm[co] += __shfl_xor_sync(0xFFFFFFFF, sm[co], off);
                sq[co] += __shfl_xor_sync(0xFFFFFFFF, sq[co], off);
            }
        if (ln == 0) {
#pragma unroll
            for (int co = 0; co < 16; ++co) {
                s_red[wid][co] = sm[co];
                s_red[wid][16 + co] = sq[co];
            }
        }
    }
    __syncthreads();
    if (t < 32) {
        float v = 0.f;
#pragma unroll
        for (int w8 = 0; w8 < 8; ++w8) v += s_red[w8][t];
        int cta = (z*16 + blockIdx.y)*16 + blockIdx.x;
        if (t < 16) g_ps1[cta*16 + t] = v;
        else        g_ps2[cta*16 + (t - 16)] = v;
    }
    // ---- direct contiguous channel-block store (no transpose needed) ----
    __half* op = g_actA + ((size_t)(b*PW + y0 + ty + 2)*PW + x0 + tx + 2)*128 + m*16;
#pragma unroll
    for (int hh = 0; hh < 2; ++hh) {
        __half tmp[8];
#pragma unroll
        for (int k = 0; k < 8; ++k) tmp[k] = __float2half(acc[hh*8 + k]);
        *(uint4*)(op + hh*8) = *(uint4*)tmp;
    }
}

// BN0 finalize from lift partials (4096 CTAs x 16 ci)
__global__ void stats_final_lift(const float* __restrict__ g, const float* __restrict__ b) {
    int c = blockIdx.x, t = threadIdx.x;
    float s = 0.f, ss = 0.f;
    for (int cta = t; cta < 4096; cta += 256) { s += g_ps1[cta*16 + c]; ss += g_ps2[cta*16 + c]; }
    __shared__ float sh1[256], sh2[256];
    sh1[t] = s; sh2[t] = ss;
    __syncthreads();
    for (int off = 128; off > 0; off >>= 1) {
        if (t < off) { sh1[t] += sh1[t + off]; sh2[t] += sh2[t + off]; }
        __syncthreads();
    }
    if (t == 0) {
        const float invN = 1.0f / 1048576.0f;
        float mean = sh1[0] * invN;
        float var  = sh2[0] * invN - mean * mean;
        float sc = g[c] * rsqrtf(var + 1e-5f);
        g_sc[c] = sc;
        g_bi[c] = b[c] - mean * sc;
    }
}

// BN stats from MMA epilogue partials (1024 tiles x 128 p, p = m*16+co)
__global__ void stats_final_mma(const float* __restrict__ g, const float* __restrict__ b) {
    int c = blockIdx.x, t = threadIdx.x;
    float s = 0.f, ss = 0.f;
    for (int e = t; e < 8192; e += 256) {
        int idx = (e >> 3) * 128 + ((e & 7) << 4) + c;
        s += g_ps1[idx]; ss += g_ps2[idx];
    }
    __shared__ float sh1[256], sh2[256];
    sh1[t] = s; sh2[t] = ss;
    __syncthreads();
    for (int off = 128; off > 0; off >>= 1) {
        if (t < off) { sh1[t] += sh1[t + off]; sh2[t] += sh2[t + off]; }
        __syncthreads();
    }
    if (t == 0) {
        const float invN = 1.0f / 1048576.0f;
        float mean = sh1[0] * invN;
        float var  = sh2[0] * invN - mean * mean;
        float sc = g[c] * rsqrtf(var + 1e-5f);
        g_sc[c] = sc;
        g_bi[c] = b[c] - mean * sc;
    }
}

// ---------------- raw mirror border copy ----------------
__global__ void border_copy_kernel(int which) {   // grid (129, 2), block 256
    __half* act = which ? g_actB : g_actA;
    int gid = blockIdx.x * 256 + threadIdx.x;
    if (gid >= 2064*16) return;
    int b = blockIdx.y;
    int i = gid >> 4, qc = gid & 15;
    int py, px;
    if (i < 520)       { py = i / 260;                 px = i % 260; }
    else if (i < 1040) { int j = i - 520; py = 258 + j / 260; px = j % 260; }
    else               { int j = i - 1040; py = 2 + (j >> 2); int c = j & 3; px = (c & 1) + ((c >> 1) * 258); }
    int uy = py - 2; uy = uy < 0 ? -uy : (uy > 255 ? 510 - uy : uy);
    int ux = px - 2; ux = ux < 0 ? -ux : (ux > 255 ? 510 - ux : ux);
    uint4 v = *(uint4*)(act + ((size_t)(b*PW + uy + 2)*PW + ux + 2)*128 + qc*8);
    *(uint4*)(act + ((size_t)(b*PW + py)*PW + px)*128 + qc*8) = v;
}

// ---------------- mma.sync implicit-GEMM conv, 128px tiles, single-buffer B, occ 2 ----------------
#define BSTG 33792   // 132 px x 256 B
__global__ __launch_bounds__(256, 2) void mma_conv_kernel(int dir, int is1x1) {
    extern __shared__ __align__(256) char dsm[];
    uint32_t sbase = smem_u32(dsm);
    uint32_t Wbase = sbase + BSTG;
    float* s_sum = (float*)(dsm + BSTG + 65536);   // [2][128]
    float* s_sq  = (float*)(dsm + BSTG + 65536 + 1024);

    const __half* actin = dir ? g_actB : g_actA;
    __half* actout      = dir ? g_actA : g_actB;

    int tid = threadIdx.x, w = tid >> 5, lane = tid & 31;
    int mw = w & 3, nw = w >> 2;
    int tile = blockIdx.x;
    int b = tile >> 9, rem = tile & 511;
    int y = rem >> 1, xh = (rem & 1) << 7;
    int ntap = is1x1 ? 1 : 25;
    const __half* wsrc = is1x1 ? g_wA4 : g_wA;
    const __half* actb = actin + (size_t)b * PW * PW * 128;

    float d[2][8][4];
#pragma unroll
    for (int mi = 0; mi < 2; ++mi)
#pragma unroll
        for (int nn = 0; nn < 8; ++nn)
#pragma unroll
            for (int k = 0; k < 4; ++k) d[mi][nn][k] = 0.f;

    auto load_brow = [&](int ky) {
        const __half* src = actb + ((size_t)(y + ky) * PW + xh) * 128;
        for (int id = tid; id < 2112; id += 256) {
            int r = id >> 4, c = id & 15;
            cp_async16(sbase + r*256 + ((c ^ (r & 7)) * 16), src + id*8);
        }
    };
    auto load_w = [&](int tp, int stg) {
        const __half* src = wsrc + tp * 16384;
        uint32_t Ab = Wbase + (uint32_t)stg * 32768;
#pragma unroll
        for (int it = 0; it < 8; ++it) {
            int id = it*256 + tid; int r = id >> 4, c = id & 15;
            cp_async16(Ab + r*256 + ((c ^ (r & 7)) * 16), src + id*8);
        }
    };
    auto bn_stage = [&]() {
        for (int id = tid; id < 2112; id += 256) {
            int r = id >> 4, c = id & 15;
            uint32_t ad = sbase + r*256 + ((c ^ (r & 7)) * 16);
            uint4 v; asm volatile("ld.shared.v4.b32 {%0,%1,%2,%3}, [%4];"
                : "=r"(v.x), "=r"(v.y), "=r"(v.z), "=r"(v.w) : "r"(ad));
            __half* h = (__half*)&v;
            int cbase = (c & 1) << 3;
#pragma unroll
            for (int k = 0; k < 8; ++k)
                h[k] = __float2half(fmaxf(fmaf(__half2float(h[k]), g_sc[cbase + k], g_bi[cbase + k]), 0.f));
            asm volatile("st.shared.v4.b32 [%0], {%1,%2,%3,%4};"
                :: "r"(ad), "r"(v.x), "r"(v.y), "r"(v.z), "r"(v.w));
        }
    };

    load_brow(is1x1 ? 2 : 0);
    load_w(0, 0);
    asm volatile("cp.async.commit_group;" ::: "memory");

#pragma unroll 1
    for (int t = 0; t < ntap; ++t) {
        int kx = is1x1 ? 2 : t % 5;
        if (t + 1 < ntap) {
            load_w(t + 1, (t + 1) & 1);
            asm volatile("cp.async.commit_group;" ::: "memory");
            asm volatile("cp.async.wait_group 1;" ::: "memory");
        } else {
            asm volatile("cp.async.wait_group 0;" ::: "memory");
        }
        __syncthreads();
        if ((t % 5) == 0) {
            bn_stage();
            __syncthreads();
        }
        uint32_t Ab = Wbase + (uint32_t)(t & 1) * 32768;
        int arb = mw*32 + (lane & 15);
        int acs = lane >> 4;
        int brb = kx + nw*64 + (lane & 7) + ((lane >> 4) << 3);
        int bcs = (lane >> 3) & 1;
#pragma unroll
        for (int ks = 0; ks < 8; ++ks) {
            uint32_t a[2][4];
#pragma unroll
            for (int mi = 0; mi < 2; ++mi) {
                int r = arb + mi*16, c = ks*2 + acs;
                ldm_x4(a[mi], Ab + r*256 + ((c ^ (r & 7)) * 16));
            }
            uint32_t bf[8][2];
#pragma unroll
            for (int nj = 0; nj < 4; ++nj) {
                int r = brb + nj*16, c = ks*2 + bcs;
                uint32_t q[4];
                ldm_x4(q, sbase + r*256 + ((c ^ (r & 7)) * 16));
                bf[nj*2][0] = q[0]; bf[nj*2][1] = q[1];
                bf[nj*2+1][0] = q[2]; bf[nj*2+1][1] = q[3];
            }
#pragma unroll
            for (int mi = 0; mi < 2; ++mi)
#pragma unroll
                for (int nn = 0; nn < 8; ++nn)
                    mma16816(d[mi][nn], a[mi], bf[nn]);
        }
        __syncthreads();
        if (!is1x1 && (t + 1) % 5 == 0 && t + 1 < ntap) {
            load_brow((t + 1) / 5);
            asm volatile("cp.async.commit_group;" ::: "memory");
        }
    }

    // ---- deterministic per-p sums ----
    int g = lane >> 2, q4 = lane & 3;
    float psum[4], psq[4];
#pragma unroll
    for (int i = 0; i < 4; ++i) { psum[i] = 0.f; psq[i] = 0.f; }
#pragma unroll
    for (int mi = 0; mi < 2; ++mi)
#pragma unroll
        for (int hh = 0; hh < 2; ++hh) {
            int pidx = mi*2 + hh;
#pragma unroll
            for (int nn = 0; nn < 8; ++nn) {
                float v0 = d[mi][nn][hh*2 + 0], v1 = d[mi][nn][hh*2 + 1];
                psum[pidx] += v0 + v1;
                psq[pidx]  += v0*v0 + v1*v1;
            }
        }
#pragma unroll
    for (int i = 0; i < 4; ++i) {
        psum[i] += __shfl_xor_sync(0xFFFFFFFF, psum[i], 1);
        psum[i] += __shfl_xor_sync(0xFFFFFFFF, psum[i], 2);
        psq[i]  += __shfl_xor_sync(0xFFFFFFFF, psq[i], 1);
        psq[i]  += __shfl_xor_sync(0xFFFFFFFF, psq[i], 2);
    }
    if (q4 == 0) {
#pragma unroll
        for (int mi = 0; mi < 2; ++mi)
#pragma unroll
            for (int hh = 0; hh < 2; ++hh) {
                int p = mw*32 + mi*16 + hh*8 + g;
                s_sum[nw*128 + p] = psum[mi*2 + hh];
                s_sq[nw*128 + p]  = psq[mi*2 + hh];
            }
    }
    // ---- transpose D -> raw fp16 NHWC via smem (reuse B + W0 area) ----
    __half* s_out = (__half*)dsm;
#pragma unroll
    for (int mi = 0; mi < 2; ++mi)
#pragma unroll
        for (int hh = 0; hh < 2; ++hh) {
            int p = mw*32 + mi*16 + hh*8 + g;
#pragma unroll
            for (int nn = 0; nn < 8; ++nn) {
                int px = nw*64 + nn*8 + q4*2;
                s_out[(size_t)px*136 + p]     = __float2half(d[mi][nn][hh*2 + 0]);
                s_out[(size_t)(px+1)*136 + p] = __float2half(d[mi][nn][hh*2 + 1]);
            }
        }
    __syncthreads();
    if (tid < 128) {
        g_ps1[tile*128 + tid] = s_sum[tid] + s_sum[128 + tid];
        g_ps2[tile*128 + tid] = s_sq[tid]  + s_sq[128 + tid];
    }
    __half* ob = actout + ((size_t)(b*PW + y + 2)*PW + 2 + xh)*128;
    for (int id = tid; id < 2048; id += 256) {
        int px = id >> 4, qc = id & 15;
        *(uint4*)(ob + (size_t)px*128 + qc*8) = *(uint4*)((char*)dsm + px*272 + qc*16);
    }
}

// ---------------- final: BN4+ReLU, max over m, 1x1 + sigmoid (conv4 raw fp16 in actA) ----------------
__global__ void final_kernel(const float* __restrict__ fw, float* __restrict__ out) {
    int gid = blockIdx.x * 256 + threadIdx.x;    // 131072
    int b = gid >> 16, pix = gid & 65535;
    int y = pix >> 8, x = pix & 255;
    const __half* p = g_actA + ((size_t)(b*PW + y + 2)*PW + x + 2)*128;
    float sc[16], bi[16], mv[16];
#pragma unroll
    for (int ci = 0; ci < 16; ++ci) { sc[ci] = g_sc[ci]; bi[ci] = g_bi[ci]; mv[ci] = 0.f; }
#pragma unroll 1
    for (int m = 0; m < 8; ++m) {
        uint4 v0 = *(const uint4*)(p + m*16);
        uint4 v1 = *(const uint4*)(p + m*16 + 8);
        const __half* h0 = (const __half*)&v0;
        const __half* h1 = (const __half*)&v1;
#pragma unroll
        for (int k = 0; k < 8; ++k) {
            mv[k]     = fmaxf(mv[k],     fmaf(__half2float(h0[k]), sc[k],     bi[k]));
            mv[8 + k] = fmaxf(mv[8 + k], fmaf(__half2float(h1[k]), sc[8 + k], bi[8 + k]));
        }
    }
    float acc = 0.f;
#pragma unroll
    for (int ci = 0; ci < 16; ++ci) acc = fmaf(fw[ci], mv[ci], acc);
    out[gid] = 1.0f / (1.0f + expf(-acc));
}

// ---------------- launch ----------------
extern "C" void kernel_launch(void* const* d_in, const int* in_sizes, int n_in,
                              void* d_out, int out_size) {
    const float* x  = (const float*)d_in[0];
    const float* lw = (const float*)d_in[1];
    const float* w1 = (const float*)d_in[2];
    const float* w2 = (const float*)d_in[3];
    const float* w3 = (const float*)d_in[4];
    const float* w4 = (const float*)d_in[5];
    const float* fw = (const float*)d_in[6];
    const float* g0 = (const float*)d_in[7];  const float* b0 = (const float*)d_in[8];
    const float* g1 = (const float*)d_in[9];  const float* b1 = (const float*)d_in[10];
    const float* g2 = (const float*)d_in[11]; const float* b2 = (const float*)d_in[12];
    const float* g3 = (const float*)d_in[13]; const float* b3 = (const float*)d_in[14];
    const float* g4 = (const float*)d_in[15]; const float* b4 = (const float*)d_in[16];
    float* out = (float*)d_out;

    const int SMEM = 101376;   // B window 33792 + 2 W stages 65536 + sums 2048
    cudaFuncSetAttribute(mma_conv_kernel, cudaFuncAttributeMaxDynamicSharedMemorySize, SMEM);

    // lift -> raw fp16 actA interior + BN0 partials; finalize + borders
    rotate_lift_kernel<<<74, 256>>>(lw);
    lift_kernel<<<dim3(16,16,16), 256>>>(x);
    stats_final_lift<<<16, 256>>>(g0, b0);
    border_copy_kernel<<<dim3(129,2), 256>>>(0);

    // layer1: actA(raw, BN0 in-load) -> actB raw
    pack_g_kernel<<<1600, 256>>>(w1);
    mma_conv_kernel<<<1024, 256, SMEM>>>(0, 0);
    stats_final_mma<<<16, 256>>>(g1, b1);
    border_copy_kernel<<<dim3(129,2), 256>>>(1);

    // layer2: actB(raw, BN1 in-load) -> actA raw
    pack_g_kernel<<<1600, 256>>>(w2);
    mma_conv_kernel<<<1024, 256, SMEM>>>(1, 0);
    stats_final_mma<<<16, 256>>>(g2, b2);
    border_copy_kernel<<<dim3(129,2), 256>>>(0);

    // layer3: actA(raw, BN2 in-load) -> actB raw
    pack_g_kernel<<<1600, 256>>>(w3);
    mma_conv_kernel<<<1024, 256, SMEM>>>(0, 0);
    stats_final_mma<<<16, 256>>>(g3, b3);
    border_copy_kernel<<<dim3(129,2), 256>>>(1);

    // conv4 (1x1): actB(raw, BN3 in-load) -> actA raw; BN4 folded into final
    pack_w4_kernel<<<64, 256>>>(w4);
    mma_conv_kernel<<<1024, 256, SMEM>>>(1, 1);
    stats_final_mma<<<16, 256>>>(g4, b4);

    final_kernel<<<512, 256>>>(fw, out);
}

// round 11
// speedup vs baseline: 1.2446x; 1.2446x over previous
#include <cuda_runtime.h>
#include <cuda_fp16.h>
#include <math.h>
#include <stdint.h>

#define HW 65536
#define PW 260

// ---------------- device scratch (allocation-free) ----------------
// Channel layout everywhere: q = o*16 + ci   (o = orientation, ci = base channel)
__device__ __align__(1024) __half g_actA[2*PW*PW*128];    // padded NHWC fp16 RAW (ping)
__device__ __align__(1024) __half g_actB[2*PW*PW*128];    // padded NHWC fp16 RAW (pong)
__device__ __align__(1024) __half g_wA[25*16384];         // gconv weights [tap][p][q] fp16
__device__ __align__(1024) __half g_wA4[16384];           // conv4 weights [p][q] fp16
__device__ __align__(1024) __half g_wL[7*4096];           // lift weights [ky][p][32] fp16
__device__ float g_ps1[1024*128], g_ps2[1024*128];        // stats partials
__device__ float g_sc[16], g_bi[16];

// ---------------- PTX helpers (sm_80-era, portable to plain sm_103) ----------------
__device__ __forceinline__ uint32_t smem_u32(const void* p) {
    uint32_t a;
    asm("{ .reg .u64 t; cvta.to.shared.u64 t, %1; cvt.u32.u64 %0, t; }" : "=r"(a) : "l"(p));
    return a;
}
__device__ __forceinline__ void cp_async16(uint32_t s, const void* g) {
    asm volatile("cp.async.cg.shared.global [%0], [%1], 16;" :: "r"(s), "l"(g) : "memory");
}
__device__ __forceinline__ void ldm_x4(uint32_t* r, uint32_t a) {
    asm volatile("ldmatrix.sync.aligned.m8n8.x4.shared.b16 {%0,%1,%2,%3}, [%4];"
        : "=r"(r[0]), "=r"(r[1]), "=r"(r[2]), "=r"(r[3]) : "r"(a));
}
__device__ __forceinline__ void mma16816(float* d, const uint32_t* a, const uint32_t* b) {
    asm volatile("mma.sync.aligned.m16n8k16.row.col.f32.f16.f16.f32 "
        "{%0,%1,%2,%3}, {%4,%5,%6,%7}, {%8,%9}, {%0,%1,%2,%3};"
        : "+f"(d[0]), "+f"(d[1]), "+f"(d[2]), "+f"(d[3])
        : "r"(a[0]), "r"(a[1]), "r"(a[2]), "r"(a[3]), "r"(b[0]), "r"(b[1]));
}
__device__ __forceinline__ void sts128(uint32_t a, uint4 v) {
    asm volatile("st.shared.v4.b32 [%0],{%1,%2,%3,%4};" :: "r"(a),"r"(v.x),"r"(v.y),"r"(v.z),"r"(v.w));
}

// ---------------- bilinear kernel rotation ----------------
__device__ __forceinline__ float rot_sample(const float* W, int k, float cs, float sn, int i, int j) {
    float c  = 0.5f * (float)(k - 1);
    float ys = (float)i - c, xs = (float)j - c;
    float sy = cs * ys - sn * xs + c;
    float sx = sn * ys + cs * xs + c;
    float fy = floorf(sy), fx = floorf(sx);
    int y0 = (int)fy, x0 = (int)fx;
    float wy = sy - fy, wx = sx - fx;
    float v00 = (y0   >= 0 && y0   < k && x0   >= 0 && x0   < k) ? W[y0*k + x0]       : 0.f;
    float v01 = (y0   >= 0 && y0   < k && x0+1 >= 0 && x0+1 < k) ? W[y0*k + x0 + 1]   : 0.f;
    float v10 = (y0+1 >= 0 && y0+1 < k && x0   >= 0 && x0   < k) ? W[(y0+1)*k + x0]   : 0.f;
    float v11 = (y0+1 >= 0 && y0+1 < k && x0+1 >= 0 && x0+1 < k) ? W[(y0+1)*k + x0+1] : 0.f;
    return v00*(1.f-wy)*(1.f-wx) + v01*(1.f-wy)*wx + v10*wy*(1.f-wx) + v11*wy*wx;
}

// pack lift weights: g_wL[ky][p=m*16+co][k=kx*3+ci (21 used, pad 32)]
__global__ void pack_lift_kernel(const float* __restrict__ lw) {
    int idx = blockIdx.x * 256 + threadIdx.x;   // 28672 = 112 blocks
    int ky = idx >> 12;
    int p  = (idx >> 5) & 127;
    int k  = idx & 31;
    int m = p >> 4, co = p & 15;
    float v = 0.f;
    if (k < 21) {
        int kx = k / 3, ci = k - kx*3;
        float th = (float)m * 0.78539816339744831f;
        v = rot_sample(lw + (co*3 + ci)*49, 7, cosf(th), sinf(th), ky, kx);
    }
    g_wL[idx] = __float2half(v);
}

// pack gconv weights: A[tap][p=m*16+co][q=o*16+ci]
__global__ void pack_g_kernel(const float* __restrict__ w) {
    int idx = blockIdx.x * 256 + threadIdx.x;   // 409600 exact
    int tap = idx >> 14;
    int p = (idx >> 7) & 127, q = idx & 127;
    int m = p >> 4, co = p & 15, o = q >> 4, ci = q & 15;
    int oo = (o - m) & 7;
    float th = (float)m * 0.78539816339744831f;
    float cs = cosf(th), sn = sinf(th);
    float v = rot_sample(w + ((co*16 + ci)*8 + oo)*25, 5, cs, sn, tap/5, tap%5);
    g_wA[tap*16384 + p*128 + q] = __float2half(v);
}

__global__ void pack_w4_kernel(const float* __restrict__ w4) {
    int idx = blockIdx.x * 256 + threadIdx.x;   // 16384
    int p = idx >> 7, q = idx & 127;
    int m = p >> 4, co = p & 15, o = q >> 4, ci = q & 15;
    g_wA4[idx] = __float2half(w4[(co*16 + ci)*8 + ((o - m) & 7)]);
}

// ---------------- lift as HMMA implicit GEMM: x -> g_actA raw fp16 interior + BN0 partials ----
// D[p=128][px=128] = sum_ky W_ky[128x32] * B_ky[128x32], K packs (kx 0..6, ci 0..2).
// SMEM: B 16KB | W 2x16KB | raw 2KB | sums 2KB = 53248.
__global__ __launch_bounds__(256, 2) void lift_mma_kernel(const float* __restrict__ x) {
    extern __shared__ __align__(256) char dsm[];
    uint32_t sbase = smem_u32(dsm);
    uint32_t Wb = sbase + 16384;
    float* s_raw = (float*)(dsm + 49152);
    float* s_sum = (float*)(dsm + 51200);
    float* s_sq  = (float*)(dsm + 52224);

    int tid = threadIdx.x, w = tid >> 5, lane = tid & 31;
    int mw = w & 3, nw = w >> 2;
    int tile = blockIdx.x;
    int b = tile >> 9, rem = tile & 511;
    int y = rem >> 1, xh = (rem & 1) << 7;

    float d[2][8][4];
#pragma unroll
    for (int mi = 0; mi < 2; ++mi)
#pragma unroll
        for (int nn = 0; nn < 8; ++nn)
#pragma unroll
            for (int k = 0; k < 4; ++k) d[mi][nn][k] = 0.f;

    auto load_w = [&](int ky, int stg) {
        const __half* src = g_wL + ky * 4096;
        uint32_t Ab = Wb + (uint32_t)stg * 16384;
#pragma unroll
        for (int i = 0; i < 2; ++i) {
            int id = i*256 + tid;            // 512 chunks: r=p, c<4
            int r = id >> 2, c = id & 3;
            cp_async16(Ab + r*128 + ((c ^ (r & 7)) * 16), src + id*8);
        }
    };

    load_w(0, 0);
    asm volatile("cp.async.commit_group;" ::: "memory");

#pragma unroll 1
    for (int ky = 0; ky < 7; ++ky) {
        int yy = y + ky - 3; yy = yy < 0 ? -yy : (yy > 255 ? 510 - yy : yy);
        for (int id = tid; id < 402; id += 256) {
            int ci = id / 134, ix = id - ci*134;
            int gx = xh + ix - 3; gx = gx < 0 ? -gx : (gx > 255 ? 510 - gx : gx);
            s_raw[id] = x[(b*3 + ci)*HW + yy*256 + gx];
        }
        if (ky + 1 < 7) {
            load_w(ky + 1, (ky + 1) & 1);
            asm volatile("cp.async.commit_group;" ::: "memory");
            asm volatile("cp.async.wait_group 1;" ::: "memory");
        } else {
            asm volatile("cp.async.wait_group 0;" ::: "memory");
        }
        __syncthreads();                       // W(ky), s_raw visible
        // build B[px][32k] (swizzled 128B rows), k = kx*3+ci, zeros for k>=21
#pragma unroll
        for (int i = 0; i < 2; ++i) {
            int cid = i*256 + tid;             // 512 chunks: px=cid>>2, c=cid&3
            int px = cid >> 2, c = cid & 3;
            __half vals[8];
#pragma unroll
            for (int j = 0; j < 8; ++j) {
                int k = c*8 + j;
                float f = 0.f;
                if (k < 21) { int kx = k/3; int ci = k - kx*3; f = s_raw[ci*134 + px + kx]; }
                vals[j] = __float2half(f);
            }
            sts128(sbase + px*128 + ((c ^ (px & 7)) * 16), *(uint4*)vals);
        }
        __syncthreads();                       // B visible
        uint32_t Ab = Wb + (uint32_t)(ky & 1) * 16384;
        int arb = mw*32 + (lane & 15);
        int acs = lane >> 4;
        int brb = nw*64 + (lane & 7) + ((lane >> 4) << 3);
        int bcs = (lane >> 3) & 1;
#pragma unroll
        for (int ks = 0; ks < 2; ++ks) {
            uint32_t a[2][4];
#pragma unroll
            for (int mi = 0; mi < 2; ++mi) {
                int r = arb + mi*16, c = ks*2 + acs;
                ldm_x4(a[mi], Ab + r*128 + ((c ^ (r & 7)) * 16));
            }
            uint32_t bf[8][2];
#pragma unroll
            for (int nj = 0; nj < 4; ++nj) {
                int r = brb + nj*16, c = ks*2 + bcs;
                uint32_t q[4];
                ldm_x4(q, sbase + r*128 + ((c ^ (r & 7)) * 16));
                bf[nj*2][0] = q[0]; bf[nj*2][1] = q[1];
                bf[nj*2+1][0] = q[2]; bf[nj*2+1][1] = q[3];
            }
#pragma unroll
            for (int mi = 0; mi < 2; ++mi)
#pragma unroll
                for (int nn = 0; nn < 8; ++nn)
                    mma16816(d[mi][nn], a[mi], bf[nn]);
        }
        __syncthreads();                       // before B/W overwrite
    }

    // ---- epilogue: stats partials + raw fp16 NHWC store (same as gconv) ----
    int g = lane >> 2, q4 = lane & 3;
    float psum[4], psq[4];
#pragma unroll
    for (int i = 0; i < 4; ++i) { psum[i] = 0.f; psq[i] = 0.f; }
#pragma unroll
    for (int mi = 0; mi < 2; ++mi)
#pragma unroll
        for (int hh = 0; hh < 2; ++hh) {
            int pidx = mi*2 + hh;
#pragma unroll
            for (int nn = 0; nn < 8; ++nn) {
                float v0 = d[mi][nn][hh*2 + 0], v1 = d[mi][nn][hh*2 + 1];
                psum[pidx] += v0 + v1;
                psq[pidx]  += v0*v0 + v1*v1;
            }
        }
#pragma unroll
    for (int i = 0; i < 4; ++i) {
        psum[i] += __shfl_xor_sync(0xFFFFFFFF, psum[i], 1);
        psum[i] += __shfl_xor_sync(0xFFFFFFFF, psum[i], 2);
        psq[i]  += __shfl_xor_sync(0xFFFFFFFF, psq[i], 1);
        psq[i]  += __shfl_xor_sync(0xFFFFFFFF, psq[i], 2);
    }
    if (q4 == 0) {
#pragma unroll
        for (int mi = 0; mi < 2; ++mi)
#pragma unroll
            for (int hh = 0; hh < 2; ++hh) {
                int p = mw*32 + mi*16 + hh*8 + g;
                s_sum[nw*128 + p] = psum[mi*2 + hh];
                s_sq[nw*128 + p]  = psq[mi*2 + hh];
            }
    }
    __half* s_out = (__half*)dsm;              // 128 px x 136-half stride (34816 B < 49152)
#pragma unroll
    for (int mi = 0; mi < 2; ++mi)
#pragma unroll
        for (int hh = 0; hh < 2; ++hh) {
            int p = mw*32 + mi*16 + hh*8 + g;
#pragma unroll
            for (int nn = 0; nn < 8; ++nn) {
                int px = nw*64 + nn*8 + q4*2;
                s_out[(size_t)px*136 + p]     = __float2half(d[mi][nn][hh*2 + 0]);
                s_out[(size_t)(px+1)*136 + p] = __float2half(d[mi][nn][hh*2 + 1]);
            }
        }
    __syncthreads();
    if (tid < 128) {
        g_ps1[tile*128 + tid] = s_sum[tid] + s_sum[128 + tid];
        g_ps2[tile*128 + tid] = s_sq[tid]  + s_sq[128 + tid];
    }
    __half* ob = g_actA + ((size_t)(b*PW + y + 2)*PW + 2 + xh)*128;
    for (int id = tid; id < 2048; id += 256) {
        int px = id >> 4, qc = id & 15;
        *(uint4*)(ob + (size_t)px*128 + qc*8) = *(uint4*)((char*)dsm + px*272 + qc*16);
    }
}

// BN stats from MMA epilogue partials (1024 tiles x 128 p, p = m*16+co); also BN0
__global__ void stats_final_mma(const float* __restrict__ g, const float* __restrict__ b) {
    int c = blockIdx.x, t = threadIdx.x;
    float s = 0.f, ss = 0.f;
    for (int e = t; e < 8192; e += 256) {
        int idx = (e >> 3) * 128 + ((e & 7) << 4) + c;
        s += g_ps1[idx]; ss += g_ps2[idx];
    }
    __shared__ float sh1[256], sh2[256];
    sh1[t] = s; sh2[t] = ss;
    __syncthreads();
    for (int off = 128; off > 0; off >>= 1) {
        if (t < off) { sh1[t] += sh1[t + off]; sh2[t] += sh2[t + off]; }
        __syncthreads();
    }
    if (t == 0) {
        const float invN = 1.0f / 1048576.0f;
        float mean = sh1[0] * invN;
        float var  = sh2[0] * invN - mean * mean;
        float sc = g[c] * rsqrtf(var + 1e-5f);
        g_sc[c] = sc;
        g_bi[c] = b[c] - mean * sc;
    }
}

// ---------------- raw mirror border copy ----------------
__global__ void border_copy_kernel(int which) {   // grid (129, 2), block 256
    __half* act = which ? g_actB : g_actA;
    int gid = blockIdx.x * 256 + threadIdx.x;
    if (gid >= 2064*16) return;
    int b = blockIdx.y;
    int i = gid >> 4, qc = gid & 15;
    int py, px;
    if (i < 520)       { py = i / 260;                 px = i % 260; }
    else if (i < 1040) { int j = i - 520; py = 258 + j / 260; px = j % 260; }
    else               { int j = i - 1040; py = 2 + (j >> 2); int c = j & 3; px = (c & 1) + ((c >> 1) * 258); }
    int uy = py - 2; uy = uy < 0 ? -uy : (uy > 255 ? 510 - uy : uy);
    int ux = px - 2; ux = ux < 0 ? -ux : (ux > 255 ? 510 - ux : ux);
    uint4 v = *(uint4*)(act + ((size_t)(b*PW + uy + 2)*PW + ux + 2)*128 + qc*8);
    *(uint4*)(act + ((size_t)(b*PW + py)*PW + px)*128 + qc*8) = v;
}

// ---------------- mma.sync implicit-GEMM conv, 128px tiles, single-buffer B, occ 2 ----------------
#define BSTG 33792   // 132 px x 256 B
__global__ __launch_bounds__(256, 2) void mma_conv_kernel(int dir, int is1x1) {
    extern __shared__ __align__(256) char dsm[];
    uint32_t sbase = smem_u32(dsm);
    uint32_t Wbase = sbase + BSTG;
    float* s_sum = (float*)(dsm + BSTG + 65536);   // [2][128]
    float* s_sq  = (float*)(dsm + BSTG + 65536 + 1024);

    const __half* actin = dir ? g_actB : g_actA;
    __half* actout      = dir ? g_actA : g_actB;

    int tid = threadIdx.x, w = tid >> 5, lane = tid & 31;
    int mw = w & 3, nw = w >> 2;
    int tile = blockIdx.x;
    int b = tile >> 9, rem = tile & 511;
    int y = rem >> 1, xh = (rem & 1) << 7;
    int ntap = is1x1 ? 1 : 25;
    const __half* wsrc = is1x1 ? g_wA4 : g_wA;
    const __half* actb = actin + (size_t)b * PW * PW * 128;

    float d[2][8][4];
#pragma unroll
    for (int mi = 0; mi < 2; ++mi)
#pragma unroll
        for (int nn = 0; nn < 8; ++nn)
#pragma unroll
            for (int k = 0; k < 4; ++k) d[mi][nn][k] = 0.f;

    auto load_brow = [&](int ky) {
        const __half* src = actb + ((size_t)(y + ky) * PW + xh) * 128;
        for (int id = tid; id < 2112; id += 256) {
            int r = id >> 4, c = id & 15;
            cp_async16(sbase + r*256 + ((c ^ (r & 7)) * 16), src + id*8);
        }
    };
    auto load_w = [&](int tp, int stg) {
        const __half* src = wsrc + tp * 16384;
        uint32_t Ab = Wbase + (uint32_t)stg * 32768;
#pragma unroll
        for (int it = 0; it < 8; ++it) {
            int id = it*256 + tid; int r = id >> 4, c = id & 15;
            cp_async16(Ab + r*256 + ((c ^ (r & 7)) * 16), src + id*8);
        }
    };
    auto bn_stage = [&]() {
        for (int id = tid; id < 2112; id += 256) {
            int r = id >> 4, c = id & 15;
            uint32_t ad = sbase + r*256 + ((c ^ (r & 7)) * 16);
            uint4 v; asm volatile("ld.shared.v4.b32 {%0,%1,%2,%3}, [%4];"
                : "=r"(v.x), "=r"(v.y), "=r"(v.z), "=r"(v.w) : "r"(ad));
            __half* h = (__half*)&v;
            int cbase = (c & 1) << 3;
#pragma unroll
            for (int k = 0; k < 8; ++k)
                h[k] = __float2half(fmaxf(fmaf(__half2float(h[k]), g_sc[cbase + k], g_bi[cbase + k]), 0.f));
            asm volatile("st.shared.v4.b32 [%0], {%1,%2,%3,%4};"
                :: "r"(ad), "r"(v.x), "r"(v.y), "r"(v.z), "r"(v.w));
        }
    };

    load_brow(is1x1 ? 2 : 0);
    load_w(0, 0);
    asm volatile("cp.async.commit_group;" ::: "memory");

#pragma unroll 1
    for (int t = 0; t < ntap; ++t) {
        int kx = is1x1 ? 2 : t % 5;
        if (t + 1 < ntap) {
            load_w(t + 1, (t + 1) & 1);
            asm volatile("cp.async.commit_group;" ::: "memory");
            asm volatile("cp.async.wait_group 1;" ::: "memory");
        } else {
            asm volatile("cp.async.wait_group 0;" ::: "memory");
        }
        __syncthreads();
        if ((t % 5) == 0) {
            bn_stage();
            __syncthreads();
        }
        uint32_t Ab = Wbase + (uint32_t)(t & 1) * 32768;
        int arb = mw*32 + (lane & 15);
        int acs = lane >> 4;
        int brb = kx + nw*64 + (lane & 7) + ((lane >> 4) << 3);
        int bcs = (lane >> 3) & 1;
#pragma unroll
        for (int ks = 0; ks < 8; ++ks) {
            uint32_t a[2][4];
#pragma unroll
            for (int mi = 0; mi < 2; ++mi) {
                int r = arb + mi*16, c = ks*2 + acs;
                ldm_x4(a[mi], Ab + r*256 + ((c ^ (r & 7)) * 16));
            }
            uint32_t bf[8][2];
#pragma unroll
            for (int nj = 0; nj < 4; ++nj) {
                int r = brb + nj*16, c = ks*2 + bcs;
                uint32_t q[4];
                ldm_x4(q, sbase + r*256 + ((c ^ (r & 7)) * 16));
                bf[nj*2][0] = q[0]; bf[nj*2][1] = q[1];
                bf[nj*2+1][0] = q[2]; bf[nj*2+1][1] = q[3];
            }
#pragma unroll
            for (int mi = 0; mi < 2; ++mi)
#pragma unroll
                for (int nn = 0; nn < 8; ++nn)
                    mma16816(d[mi][nn], a[mi], bf[nn]);
        }
        __syncthreads();
        if (!is1x1 && (t + 1) % 5 == 0 && t + 1 < ntap) {
            load_brow((t + 1) / 5);
            asm volatile("cp.async.commit_group;" ::: "memory");
        }
    }

    // ---- deterministic per-p sums ----
    int g = lane >> 2, q4 = lane & 3;
    float psum[4], psq[4];
#pragma unroll
    for (int i = 0; i < 4; ++i) { psum[i] = 0.f; psq[i] = 0.f; }
#pragma unroll
    for (int mi = 0; mi < 2; ++mi)
#pragma unroll
        for (int hh = 0; hh < 2; ++hh) {
            int pidx = mi*2 + hh;
#pragma unroll
            for (int nn = 0; nn < 8; ++nn) {
                float v0 = d[mi][nn][hh*2 + 0], v1 = d[mi][nn][hh*2 + 1];
                psum[pidx] += v0 + v1;
                psq[pidx]  += v0*v0 + v1*v1;
            }
        }
#pragma unroll
    for (int i = 0; i < 4; ++i) {
        psum[i] += __shfl_xor_sync(0xFFFFFFFF, psum[i], 1);
        psum[i] += __shfl_xor_sync(0xFFFFFFFF, psum[i], 2);
        psq[i]  += __shfl_xor_sync(0xFFFFFFFF, psq[i], 1);
        psq[i]  += __shfl_xor_sync(0xFFFFFFFF, psq[i], 2);
    }
    if (q4 == 0) {
#pragma unroll
        for (int mi = 0; mi < 2; ++mi)
#pragma unroll
            for (int hh = 0; hh < 2; ++hh) {
                int p = mw*32 + mi*16 + hh*8 + g;
                s_sum[nw*128 + p] = psum[mi*2 + hh];
                s_sq[nw*128 + p]  = psq[mi*2 + hh];
            }
    }
    __half* s_out = (__half*)dsm;
#pragma unroll
    for (int mi = 0; mi < 2; ++mi)
#pragma unroll
        for (int hh = 0; hh < 2; ++hh) {
            int p = mw*32 + mi*16 + hh*8 + g;
#pragma unroll
            for (int nn = 0; nn < 8; ++nn) {
                int px = nw*64 + nn*8 + q4*2;
                s_out[(size_t)px*136 + p]     = __float2half(d[mi][nn][hh*2 + 0]);
                s_out[(size_t)(px+1)*136 + p] = __float2half(d[mi][nn][hh*2 + 1]);
            }
        }
    __syncthreads();
    if (tid < 128) {
        g_ps1[tile*128 + tid] = s_sum[tid] + s_sum[128 + tid];
        g_ps2[tile*128 + tid] = s_sq[tid]  + s_sq[128 + tid];
    }
    __half* ob = actout + ((size_t)(b*PW + y + 2)*PW + 2 + xh)*128;
    for (int id = tid; id < 2048; id += 256) {
        int px = id >> 4, qc = id & 15;
        *(uint4*)(ob + (size_t)px*128 + qc*8) = *(uint4*)((char*)dsm + px*272 + qc*16);
    }
}

// ---------------- final: BN4+ReLU, max over m, 1x1 + sigmoid (conv4 raw fp16 in actA) ----------------
__global__ void final_kernel(const float* __restrict__ fw, float* __restrict__ out) {
    int gid = blockIdx.x * 256 + threadIdx.x;    // 131072
    int b = gid >> 16, pix = gid & 65535;
    int y = pix >> 8, x = pix & 255;
    const __half* p = g_actA + ((size_t)(b*PW + y + 2)*PW + x + 2)*128;
    float sc[16], bi[16], mv[16];
#pragma unroll
    for (int ci = 0; ci < 16; ++ci) { sc[ci] = g_sc[ci]; bi[ci] = g_bi[ci]; mv[ci] = 0.f; }
#pragma unroll 1
    for (int m = 0; m < 8; ++m) {
        uint4 v0 = *(const uint4*)(p + m*16);
        uint4 v1 = *(const uint4*)(p + m*16 + 8);
        const __half* h0 = (const __half*)&v0;
        const __half* h1 = (const __half*)&v1;
#pragma unroll
        for (int k = 0; k < 8; ++k) {
            mv[k]     = fmaxf(mv[k],     fmaf(__half2float(h0[k]), sc[k],     bi[k]));
            mv[8 + k] = fmaxf(mv[8 + k], fmaf(__half2float(h1[k]), sc[8 + k], bi[8 + k]));
        }
    }
    float acc = 0.f;
#pragma unroll
    for (int ci = 0; ci < 16; ++ci) acc = fmaf(fw[ci], mv[ci], acc);
    out[gid] = 1.0f / (1.0f + expf(-acc));
}

// ---------------- launch ----------------
extern "C" void kernel_launch(void* const* d_in, const int* in_sizes, int n_in,
                              void* d_out, int out_size) {
    const float* x  = (const float*)d_in[0];
    const float* lw = (const float*)d_in[1];
    const float* w1 = (const float*)d_in[2];
    const float* w2 = (const float*)d_in[3];
    const float* w3 = (const float*)d_in[4];
    const float* w4 = (const float*)d_in[5];
    const float* fw = (const float*)d_in[6];
    const float* g0 = (const float*)d_in[7];  const float* b0 = (const float*)d_in[8];
    const float* g1 = (const float*)d_in[9];  const float* b1 = (const float*)d_in[10];
    const float* g2 = (const float*)d_in[11]; const float* b2 = (const float*)d_in[12];
    const float* g3 = (const float*)d_in[13]; const float* b3 = (const float*)d_in[14];
    const float* g4 = (const float*)d_in[15]; const float* b4 = (const float*)d_in[16];
    float* out = (float*)d_out;

    const int SMEM  = 101376;   // gconv: B window 33792 + 2 W stages 65536 + sums 2048
    const int SMEML = 53248;    // lift:  B 16384 + 2 W 32768 + raw 2048 + sums 2048
    cudaFuncSetAttribute(mma_conv_kernel, cudaFuncAttributeMaxDynamicSharedMemorySize, SMEM);
    cudaFuncSetAttribute(lift_mma_kernel, cudaFuncAttributeMaxDynamicSharedMemorySize, SMEML);

    // lift (HMMA) -> raw fp16 actA interior + BN0 partials; finalize + borders
    pack_lift_kernel<<<112, 256>>>(lw);
    lift_mma_kernel<<<1024, 256, SMEML>>>(x);
    stats_final_mma<<<16, 256>>>(g0, b0);
    border_copy_kernel<<<dim3(129,2), 256>>>(0);

    // layer1: actA(raw, BN0 in-load) -> actB raw
    pack_g_kernel<<<1600, 256>>>(w1);
    mma_conv_kernel<<<1024, 256, SMEM>>>(0, 0);
    stats_final_mma<<<16, 256>>>(g1, b1);
    border_copy_kernel<<<dim3(129,2), 256>>>(1);

    // layer2: actB(raw, BN1 in-load) -> actA raw
    pack_g_kernel<<<1600, 256>>>(w2);
    mma_conv_kernel<<<1024, 256, SMEM>>>(1, 0);
    stats_final_mma<<<16, 256>>>(g2, b2);
    border_copy_kernel<<<dim3(129,2), 256>>>(0);

    // layer3: actA(raw, BN2 in-load) -> actB raw
    pack_g_kernel<<<1600, 256>>>(w3);
    mma_conv_kernel<<<1024, 256, SMEM>>>(0, 0);
    stats_final_mma<<<16, 256>>>(g3, b3);
    border_copy_kernel<<<dim3(129,2), 256>>>(1);

    // conv4 (1x1): actB(raw, BN3 in-load) -> actA raw; BN4 folded into final
    pack_w4_kernel<<<64, 256>>>(w4);
    mma_conv_kernel<<<1024, 256, SMEM>>>(1, 1);
    stats_final_mma<<<16, 256>>>(g4, b4);

    final_kernel<<<512, 256>>>(fw, out);
}

// round 12
// speedup vs baseline: 1.2830x; 1.0309x over previous
#include <cuda_runtime.h>
#include <cuda_fp16.h>
#include <math.h>
#include <stdint.h>

#define HW 65536
#define PW 260

// ---------------- device scratch (allocation-free) ----------------
// Channel layout everywhere: q = o*16 + ci   (o = orientation, ci = base channel)
__device__ __align__(1024) __half g_actA[2*PW*PW*128];    // padded NHWC fp16 RAW (ping)
__device__ __align__(1024) __half g_actB[2*PW*PW*128];    // padded NHWC fp16 RAW (pong)
__device__ __align__(1024) __half g_wA[25*16384];         // gconv weights [tap][p][q] fp16
__device__ __align__(1024) __half g_wA4[16384];           // conv4 weights [p][q] fp16
__device__ __align__(1024) __half g_wL[7*4096];           // lift weights [ky][p][32] fp16
__device__ float g_ps1[1024*128], g_ps2[1024*128];        // stats partials
__device__ float g_sc[16], g_bi[16];

// ---------------- PTX helpers (sm_80-era, portable to plain sm_103) ----------------
__device__ __forceinline__ uint32_t smem_u32(const void* p) {
    uint32_t a;
    asm("{ .reg .u64 t; cvta.to.shared.u64 t, %1; cvt.u32.u64 %0, t; }" : "=r"(a) : "l"(p));
    return a;
}
__device__ __forceinline__ void cp_async16(uint32_t s, const void* g) {
    asm volatile("cp.async.cg.shared.global [%0], [%1], 16;" :: "r"(s), "l"(g) : "memory");
}
__device__ __forceinline__ void ldm_x4(uint32_t* r, uint32_t a) {
    asm volatile("ldmatrix.sync.aligned.m8n8.x4.shared.b16 {%0,%1,%2,%3}, [%4];"
        : "=r"(r[0]), "=r"(r[1]), "=r"(r[2]), "=r"(r[3]) : "r"(a));
}
__device__ __forceinline__ void mma16816(float* d, const uint32_t* a, const uint32_t* b) {
    asm volatile("mma.sync.aligned.m16n8k16.row.col.f32.f16.f16.f32 "
        "{%0,%1,%2,%3}, {%4,%5,%6,%7}, {%8,%9}, {%0,%1,%2,%3};"
        : "+f"(d[0]), "+f"(d[1]), "+f"(d[2]), "+f"(d[3])
        : "r"(a[0]), "r"(a[1]), "r"(a[2]), "r"(a[3]), "r"(b[0]), "r"(b[1]));
}
__device__ __forceinline__ void sts128(uint32_t a, uint4 v) {
    asm volatile("st.shared.v4.b32 [%0],{%1,%2,%3,%4};" :: "r"(a),"r"(v.x),"r"(v.y),"r"(v.z),"r"(v.w));
}

// ---------------- bilinear kernel rotation ----------------
__device__ __forceinline__ float rot_sample(const float* W, int k, float cs, float sn, int i, int j) {
    float c  = 0.5f * (float)(k - 1);
    float ys = (float)i - c, xs = (float)j - c;
    float sy = cs * ys - sn * xs + c;
    float sx = sn * ys + cs * xs + c;
    float fy = floorf(sy), fx = floorf(sx);
    int y0 = (int)fy, x0 = (int)fx;
    float wy = sy - fy, wx = sx - fx;
    float v00 = (y0   >= 0 && y0   < k && x0   >= 0 && x0   < k) ? W[y0*k + x0]       : 0.f;
    float v01 = (y0   >= 0 && y0   < k && x0+1 >= 0 && x0+1 < k) ? W[y0*k + x0 + 1]   : 0.f;
    float v10 = (y0+1 >= 0 && y0+1 < k && x0   >= 0 && x0   < k) ? W[(y0+1)*k + x0]   : 0.f;
    float v11 = (y0+1 >= 0 && y0+1 < k && x0+1 >= 0 && x0+1 < k) ? W[(y0+1)*k + x0+1] : 0.f;
    return v00*(1.f-wy)*(1.f-wx) + v01*(1.f-wy)*wx + v10*wy*(1.f-wx) + v11*wy*wx;
}

// pack lift weights: g_wL[ky][p=m*16+co][k=kx*3+ci (21 used, pad 32)]
__global__ void pack_lift_kernel(const float* __restrict__ lw) {
    int idx = blockIdx.x * 256 + threadIdx.x;   // 28672 = 112 blocks
    int ky = idx >> 12;
    int p  = (idx >> 5) & 127;
    int k  = idx & 31;
    int m = p >> 4, co = p & 15;
    float v = 0.f;
    if (k < 21) {
        int kx = k / 3, ci = k - kx*3;
        float th = (float)m * 0.78539816339744831f;
        v = rot_sample(lw + (co*3 + ci)*49, 7, cosf(th), sinf(th), ky, kx);
    }
    g_wL[idx] = __float2half(v);
}

// pack gconv weights: A[tap][p=m*16+co][q=o*16+ci]
__global__ void pack_g_kernel(const float* __restrict__ w) {
    int idx = blockIdx.x * 256 + threadIdx.x;   // 409600 exact
    int tap = idx >> 14;
    int p = (idx >> 7) & 127, q = idx & 127;
    int m = p >> 4, co = p & 15, o = q >> 4, ci = q & 15;
    int oo = (o - m) & 7;
    float th = (float)m * 0.78539816339744831f;
    float cs = cosf(th), sn = sinf(th);
    float v = rot_sample(w + ((co*16 + ci)*8 + oo)*25, 5, cs, sn, tap/5, tap%5);
    g_wA[tap*16384 + p*128 + q] = __float2half(v);
}

__global__ void pack_w4_kernel(const float* __restrict__ w4) {
    int idx = blockIdx.x * 256 + threadIdx.x;   // 16384
    int p = idx >> 7, q = idx & 127;
    int m = p >> 4, co = p & 15, o = q >> 4, ci = q & 15;
    g_wA4[idx] = __float2half(w4[(co*16 + ci)*8 + ((o - m) & 7)]);
}

// ---------------- lift as HMMA implicit GEMM (unchanged from R11) ----------------
__global__ __launch_bounds__(256, 2) void lift_mma_kernel(const float* __restrict__ x) {
    extern __shared__ __align__(256) char dsm[];
    uint32_t sbase = smem_u32(dsm);
    uint32_t Wb = sbase + 16384;
    float* s_raw = (float*)(dsm + 49152);
    float* s_sum = (float*)(dsm + 51200);
    float* s_sq  = (float*)(dsm + 52224);

    int tid = threadIdx.x, w = tid >> 5, lane = tid & 31;
    int mw = w & 3, nw = w >> 2;
    int tile = blockIdx.x;
    int b = tile >> 9, rem = tile & 511;
    int y = rem >> 1, xh = (rem & 1) << 7;

    float d[2][8][4];
#pragma unroll
    for (int mi = 0; mi < 2; ++mi)
#pragma unroll
        for (int nn = 0; nn < 8; ++nn)
#pragma unroll
            for (int k = 0; k < 4; ++k) d[mi][nn][k] = 0.f;

    auto load_w = [&](int ky, int stg) {
        const __half* src = g_wL + ky * 4096;
        uint32_t Ab = Wb + (uint32_t)stg * 16384;
#pragma unroll
        for (int i = 0; i < 2; ++i) {
            int id = i*256 + tid;
            int r = id >> 2, c = id & 3;
            cp_async16(Ab + r*128 + ((c ^ (r & 7)) * 16), src + id*8);
        }
    };

    load_w(0, 0);
    asm volatile("cp.async.commit_group;" ::: "memory");

#pragma unroll 1
    for (int ky = 0; ky < 7; ++ky) {
        int yy = y + ky - 3; yy = yy < 0 ? -yy : (yy > 255 ? 510 - yy : yy);
        for (int id = tid; id < 402; id += 256) {
            int ci = id / 134, ix = id - ci*134;
            int gx = xh + ix - 3; gx = gx < 0 ? -gx : (gx > 255 ? 510 - gx : gx);
            s_raw[id] = x[(b*3 + ci)*HW + yy*256 + gx];
        }
        if (ky + 1 < 7) {
            load_w(ky + 1, (ky + 1) & 1);
            asm volatile("cp.async.commit_group;" ::: "memory");
            asm volatile("cp.async.wait_group 1;" ::: "memory");
        } else {
            asm volatile("cp.async.wait_group 0;" ::: "memory");
        }
        __syncthreads();
#pragma unroll
        for (int i = 0; i < 2; ++i) {
            int cid = i*256 + tid;
            int px = cid >> 2, c = cid & 3;
            __half vals[8];
#pragma unroll
            for (int j = 0; j < 8; ++j) {
                int k = c*8 + j;
                float f = 0.f;
                if (k < 21) { int kx = k/3; int ci = k - kx*3; f = s_raw[ci*134 + px + kx]; }
                vals[j] = __float2half(f);
            }
            sts128(sbase + px*128 + ((c ^ (px & 7)) * 16), *(uint4*)vals);
        }
        __syncthreads();
        uint32_t Ab = Wb + (uint32_t)(ky & 1) * 16384;
        int arb = mw*32 + (lane & 15);
        int acs = lane >> 4;
        int brb = nw*64 + (lane & 7) + ((lane >> 4) << 3);
        int bcs = (lane >> 3) & 1;
#pragma unroll
        for (int ks = 0; ks < 2; ++ks) {
            uint32_t a[2][4];
#pragma unroll
            for (int mi = 0; mi < 2; ++mi) {
                int r = arb + mi*16, c = ks*2 + acs;
                ldm_x4(a[mi], Ab + r*128 + ((c ^ (r & 7)) * 16));
            }
            uint32_t bf[8][2];
#pragma unroll
            for (int nj = 0; nj < 4; ++nj) {
                int r = brb + nj*16, c = ks*2 + bcs;
                uint32_t q[4];
                ldm_x4(q, sbase + r*128 + ((c ^ (r & 7)) * 16));
                bf[nj*2][0] = q[0]; bf[nj*2][1] = q[1];
                bf[nj*2+1][0] = q[2]; bf[nj*2+1][1] = q[3];
            }
#pragma unroll
            for (int mi = 0; mi < 2; ++mi)
#pragma unroll
                for (int nn = 0; nn < 8; ++nn)
                    mma16816(d[mi][nn], a[mi], bf[nn]);
        }
        __syncthreads();
    }

    int g = lane >> 2, q4 = lane & 3;
    float psum[4], psq[4];
#pragma unroll
    for (int i = 0; i < 4; ++i) { psum[i] = 0.f; psq[i] = 0.f; }
#pragma unroll
    for (int mi = 0; mi < 2; ++mi)
#pragma unroll
        for (int hh = 0; hh < 2; ++hh) {
            int pidx = mi*2 + hh;
#pragma unroll
            for (int nn = 0; nn < 8; ++nn) {
                float v0 = d[mi][nn][hh*2 + 0], v1 = d[mi][nn][hh*2 + 1];
                psum[pidx] += v0 + v1;
                psq[pidx]  += v0*v0 + v1*v1;
            }
        }
#pragma unroll
    for (int i = 0; i < 4; ++i) {
        psum[i] += __shfl_xor_sync(0xFFFFFFFF, psum[i], 1);
        psum[i] += __shfl_xor_sync(0xFFFFFFFF, psum[i], 2);
        psq[i]  += __shfl_xor_sync(0xFFFFFFFF, psq[i], 1);
        psq[i]  += __shfl_xor_sync(0xFFFFFFFF, psq[i], 2);
    }
    if (q4 == 0) {
#pragma unroll
        for (int mi = 0; mi < 2; ++mi)
#pragma unroll
            for (int hh = 0; hh < 2; ++hh) {
                int p = mw*32 + mi*16 + hh*8 + g;
                s_sum[nw*128 + p] = psum[mi*2 + hh];
                s_sq[nw*128 + p]  = psq[mi*2 + hh];
            }
    }
    __half* s_out = (__half*)dsm;
#pragma unroll
    for (int mi = 0; mi < 2; ++mi)
#pragma unroll
        for (int hh = 0; hh < 2; ++hh) {
            int p = mw*32 + mi*16 + hh*8 + g;
#pragma unroll
            for (int nn = 0; nn < 8; ++nn) {
                int px = nw*64 + nn*8 + q4*2;
                s_out[(size_t)px*136 + p]     = __float2half(d[mi][nn][hh*2 + 0]);
                s_out[(size_t)(px+1)*136 + p] = __float2half(d[mi][nn][hh*2 + 1]);
            }
        }
    __syncthreads();
    if (tid < 128) {
        g_ps1[tile*128 + tid] = s_sum[tid] + s_sum[128 + tid];
        g_ps2[tile*128 + tid] = s_sq[tid]  + s_sq[128 + tid];
    }
    __half* ob = g_actA + ((size_t)(b*PW + y + 2)*PW + 2 + xh)*128;
    for (int id = tid; id < 2048; id += 256) {
        int px = id >> 4, qc = id & 15;
        *(uint4*)(ob + (size_t)px*128 + qc*8) = *(uint4*)((char*)dsm + px*272 + qc*16);
    }
}

// BN stats from MMA epilogue partials (1024 tiles x 128 p, p = m*16+co)
__global__ void stats_final_mma(const float* __restrict__ g, const float* __restrict__ b) {
    int c = blockIdx.x, t = threadIdx.x;
    float s = 0.f, ss = 0.f;
    for (int e = t; e < 8192; e += 256) {
        int idx = (e >> 3) * 128 + ((e & 7) << 4) + c;
        s += g_ps1[idx]; ss += g_ps2[idx];
    }
    __shared__ float sh1[256], sh2[256];
    sh1[t] = s; sh2[t] = ss;
    __syncthreads();
    for (int off = 128; off > 0; off >>= 1) {
        if (t < off) { sh1[t] += sh1[t + off]; sh2[t] += sh2[t + off]; }
        __syncthreads();
    }
    if (t == 0) {
        const float invN = 1.0f / 1048576.0f;
        float mean = sh1[0] * invN;
        float var  = sh2[0] * invN - mean * mean;
        float sc = g[c] * rsqrtf(var + 1e-5f);
        g_sc[c] = sc;
        g_bi[c] = b[c] - mean * sc;
    }
}

// ---------------- raw mirror border copy ----------------
__global__ void border_copy_kernel(int which) {   // grid (129, 2), block 256
    __half* act = which ? g_actB : g_actA;
    int gid = blockIdx.x * 256 + threadIdx.x;
    if (gid >= 2064*16) return;
    int b = blockIdx.y;
    int i = gid >> 4, qc = gid & 15;
    int py, px;
    if (i < 520)       { py = i / 260;                 px = i % 260; }
    else if (i < 1040) { int j = i - 520; py = 258 + j / 260; px = j % 260; }
    else               { int j = i - 1040; py = 2 + (j >> 2); int c = j & 3; px = (c & 1) + ((c >> 1) * 258); }
    int uy = py - 2; uy = uy < 0 ? -uy : (uy > 255 ? 510 - uy : uy);
    int ux = px - 2; ux = ux < 0 ? -ux : (ux > 255 ? 510 - ux : ux);
    uint4 v = *(uint4*)(act + ((size_t)(b*PW + uy + 2)*PW + ux + 2)*128 + qc*8);
    *(uint4*)(act + ((size_t)(b*PW + py)*PW + px)*128 + qc*8) = v;
}

// ---------------- mma.sync implicit-GEMM conv: 4 warps x 64p x 64px, occ 2 ----------------
#define BSTG 33792   // 132 px x 256 B
__global__ __launch_bounds__(128, 2) void mma_conv_kernel(int dir, int is1x1) {
    extern __shared__ __align__(256) char dsm[];
    uint32_t sbase = smem_u32(dsm);
    uint32_t Wbase = sbase + BSTG;
    float* s_sum = (float*)(dsm + BSTG + 65536);   // [2][128]
    float* s_sq  = (float*)(dsm + BSTG + 65536 + 1024);

    const __half* actin = dir ? g_actB : g_actA;
    __half* actout      = dir ? g_actA : g_actB;

    int tid = threadIdx.x, w = tid >> 5, lane = tid & 31;
    int mw = w & 1, nw = w >> 1;
    int tile = blockIdx.x;
    int b = tile >> 9, rem = tile & 511;
    int y = rem >> 1, xh = (rem & 1) << 7;
    int ntap = is1x1 ? 1 : 25;
    const __half* wsrc = is1x1 ? g_wA4 : g_wA;
    const __half* actb = actin + (size_t)b * PW * PW * 128;

    float d[4][8][4];
#pragma unroll
    for (int mi = 0; mi < 4; ++mi)
#pragma unroll
        for (int nn = 0; nn < 8; ++nn)
#pragma unroll
            for (int k = 0; k < 4; ++k) d[mi][nn][k] = 0.f;

    auto load_brow = [&](int ky) {
        const __half* src = actb + ((size_t)(y + ky) * PW + xh) * 128;
        for (int id = tid; id < 2112; id += 128) {
            int r = id >> 4, c = id & 15;
            cp_async16(sbase + r*256 + ((c ^ (r & 7)) * 16), src + id*8);
        }
    };
    auto load_w = [&](int tp, int stg) {
        const __half* src = wsrc + tp * 16384;
        uint32_t Ab = Wbase + (uint32_t)stg * 32768;
#pragma unroll
        for (int it = 0; it < 16; ++it) {
            int id = it*128 + tid; int r = id >> 4, c = id & 15;
            cp_async16(Ab + r*256 + ((c ^ (r & 7)) * 16), src + id*8);
        }
    };
    auto bn_stage = [&]() {
        for (int id = tid; id < 2112; id += 128) {
            int r = id >> 4, c = id & 15;
            uint32_t ad = sbase + r*256 + ((c ^ (r & 7)) * 16);
            uint4 v; asm volatile("ld.shared.v4.b32 {%0,%1,%2,%3}, [%4];"
                : "=r"(v.x), "=r"(v.y), "=r"(v.z), "=r"(v.w) : "r"(ad));
            __half* h = (__half*)&v;
            int cbase = (c & 1) << 3;
#pragma unroll
            for (int k = 0; k < 8; ++k)
                h[k] = __float2half(fmaxf(fmaf(__half2float(h[k]), g_sc[cbase + k], g_bi[cbase + k]), 0.f));
            asm volatile("st.shared.v4.b32 [%0], {%1,%2,%3,%4};"
                :: "r"(ad), "r"(v.x), "r"(v.y), "r"(v.z), "r"(v.w));
        }
    };

    load_brow(is1x1 ? 2 : 0);
    load_w(0, 0);
    asm volatile("cp.async.commit_group;" ::: "memory");

#pragma unroll 1
    for (int t = 0; t < ntap; ++t) {
        int kx = is1x1 ? 2 : t % 5;
        if (t + 1 < ntap) {
            load_w(t + 1, (t + 1) & 1);
            asm volatile("cp.async.commit_group;" ::: "memory");
            asm volatile("cp.async.wait_group 1;" ::: "memory");
        } else {
            asm volatile("cp.async.wait_group 0;" ::: "memory");
        }
        __syncthreads();
        if ((t % 5) == 0) {
            bn_stage();
            __syncthreads();
        }
        uint32_t Ab = Wbase + (uint32_t)(t & 1) * 32768;
        int arb = mw*64 + (lane & 15);
        int acs = lane >> 4;
        int brb = kx + nw*64 + (lane & 7) + ((lane >> 4) << 3);
        int bcs = (lane >> 3) & 1;
#pragma unroll
        for (int ks = 0; ks < 8; ++ks) {
            uint32_t a[4][4];
#pragma unroll
            for (int mi = 0; mi < 4; ++mi) {
                int r = arb + mi*16, c = ks*2 + acs;
                ldm_x4(a[mi], Ab + r*256 + ((c ^ (r & 7)) * 16));
            }
            uint32_t bf[8][2];
#pragma unroll
            for (int nj = 0; nj < 4; ++nj) {
                int r = brb + nj*16, c = ks*2 + bcs;
                uint32_t q[4];
                ldm_x4(q, sbase + r*256 + ((c ^ (r & 7)) * 16));
                bf[nj*2][0] = q[0]; bf[nj*2][1] = q[1];
                bf[nj*2+1][0] = q[2]; bf[nj*2+1][1] = q[3];
            }
#pragma unroll
            for (int mi = 0; mi < 4; ++mi)
#pragma unroll
                for (int nn = 0; nn < 8; ++nn)
                    mma16816(d[mi][nn], a[mi], bf[nn]);
        }
        __syncthreads();
        if (!is1x1 && (t + 1) % 5 == 0 && t + 1 < ntap) {
            load_brow((t + 1) / 5);
            asm volatile("cp.async.commit_group;" ::: "memory");
        }
    }

    // ---- deterministic per-p sums ----
    int g = lane >> 2, q4 = lane & 3;
    float psum[8], psq[8];
#pragma unroll
    for (int i = 0; i < 8; ++i) { psum[i] = 0.f; psq[i] = 0.f; }
#pragma unroll
    for (int mi = 0; mi < 4; ++mi)
#pragma unroll
        for (int hh = 0; hh < 2; ++hh) {
            int pidx = mi*2 + hh;
#pragma unroll
            for (int nn = 0; nn < 8; ++nn) {
                float v0 = d[mi][nn][hh*2 + 0], v1 = d[mi][nn][hh*2 + 1];
                psum[pidx] += v0 + v1;
                psq[pidx]  += v0*v0 + v1*v1;
            }
        }
#pragma unroll
    for (int i = 0; i < 8; ++i) {
        psum[i] += __shfl_xor_sync(0xFFFFFFFF, psum[i], 1);
        psum[i] += __shfl_xor_sync(0xFFFFFFFF, psum[i], 2);
        psq[i]  += __shfl_xor_sync(0xFFFFFFFF, psq[i], 1);
        psq[i]  += __shfl_xor_sync(0xFFFFFFFF, psq[i], 2);
    }
    if (q4 == 0) {
#pragma unroll
        for (int mi = 0; mi < 4; ++mi)
#pragma unroll
            for (int hh = 0; hh < 2; ++hh) {
                int p = mw*64 + mi*16 + hh*8 + g;
                s_sum[nw*128 + p] = psum[mi*2 + hh];
                s_sq[nw*128 + p]  = psq[mi*2 + hh];
            }
    }
    // ---- transpose D -> raw fp16 NHWC via smem (reuse B + W0 area) ----
    __half* s_out = (__half*)dsm;
#pragma unroll
    for (int mi = 0; mi < 4; ++mi)
#pragma unroll
        for (int hh = 0; hh < 2; ++hh) {
            int p = mw*64 + mi*16 + hh*8 + g;
#pragma unroll
            for (int nn = 0; nn < 8; ++nn) {
                int px = nw*64 + nn*8 + q4*2;
                s_out[(size_t)px*136 + p]     = __float2half(d[mi][nn][hh*2 + 0]);
                s_out[(size_t)(px+1)*136 + p] = __float2half(d[mi][nn][hh*2 + 1]);
            }
        }
    __syncthreads();
    g_ps1[tile*128 + tid] = s_sum[tid] + s_sum[128 + tid];
    g_ps2[tile*128 + tid] = s_sq[tid]  + s_sq[128 + tid];
    __half* ob = actout + ((size_t)(b*PW + y + 2)*PW + 2 + xh)*128;
    for (int id = tid; id < 2048; id += 128) {
        int px = id >> 4, qc = id & 15;
        *(uint4*)(ob + (size_t)px*128 + qc*8) = *(uint4*)((char*)dsm + px*272 + qc*16);
    }
}

// ---------------- final: BN4+ReLU, max over m, 1x1 + sigmoid (conv4 raw fp16 in actA) ----------------
__global__ void final_kernel(const float* __restrict__ fw, float* __restrict__ out) {
    int gid = blockIdx.x * 256 + threadIdx.x;    // 131072
    int b = gid >> 16, pix = gid & 65535;
    int y = pix >> 8, x = pix & 255;
    const __half* p = g_actA + ((size_t)(b*PW + y + 2)*PW + x + 2)*128;
    float sc[16], bi[16], mv[16];
#pragma unroll
    for (int ci = 0; ci < 16; ++ci) { sc[ci] = g_sc[ci]; bi[ci] = g_bi[ci]; mv[ci] = 0.f; }
#pragma unroll 1
    for (int m = 0; m < 8; ++m) {
        uint4 v0 = *(const uint4*)(p + m*16);
        uint4 v1 = *(const uint4*)(p + m*16 + 8);
        const __half* h0 = (const __half*)&v0;
        const __half* h1 = (const __half*)&v1;
#pragma unroll
        for (int k = 0; k < 8; ++k) {
            mv[k]     = fmaxf(mv[k],     fmaf(__half2float(h0[k]), sc[k],     bi[k]));
            mv[8 + k] = fmaxf(mv[8 + k], fmaf(__half2float(h1[k]), sc[8 + k], bi[8 + k]));
        }
    }
    float acc = 0.f;
#pragma unroll
    for (int ci = 0; ci < 16; ++ci) acc = fmaf(fw[ci], mv[ci], acc);
    out[gid] = 1.0f / (1.0f + expf(-acc));
}

// ---------------- launch ----------------
extern "C" void kernel_launch(void* const* d_in, const int* in_sizes, int n_in,
                              void* d_out, int out_size) {
    const float* x  = (const float*)d_in[0];
    const float* lw = (const float*)d_in[1];
    const float* w1 = (const float*)d_in[2];
    const float* w2 = (const float*)d_in[3];
    const float* w3 = (const float*)d_in[4];
    const float* w4 = (const float*)d_in[5];
    const float* fw = (const float*)d_in[6];
    const float* g0 = (const float*)d_in[7];  const float* b0 = (const float*)d_in[8];
    const float* g1 = (const float*)d_in[9];  const float* b1 = (const float*)d_in[10];
    const float* g2 = (const float*)d_in[11]; const float* b2 = (const float*)d_in[12];
    const float* g3 = (const float*)d_in[13]; const float* b3 = (const float*)d_in[14];
    const float* g4 = (const float*)d_in[15]; const float* b4 = (const float*)d_in[16];
    float* out = (float*)d_out;

    const int SMEM  = 101376;   // gconv: B window 33792 + 2 W stages 65536 + sums 2048
    const int SMEML = 53248;    // lift:  B 16384 + 2 W 32768 + raw 2048 + sums 2048
    cudaFuncSetAttribute(mma_conv_kernel, cudaFuncAttributeMaxDynamicSharedMemorySize, SMEM);
    cudaFuncSetAttribute(lift_mma_kernel, cudaFuncAttributeMaxDynamicSharedMemorySize, SMEML);

    // lift (HMMA) -> raw fp16 actA interior + BN0 partials; finalize + borders
    pack_lift_kernel<<<112, 256>>>(lw);
    lift_mma_kernel<<<1024, 256, SMEML>>>(x);
    stats_final_mma<<<16, 256>>>(g0, b0);
    border_copy_kernel<<<dim3(129,2), 256>>>(0);

    // layer1: actA(raw, BN0 in-load) -> actB raw
    pack_g_kernel<<<1600, 256>>>(w1);
    mma_conv_kernel<<<1024, 128, SMEM>>>(0, 0);
    stats_final_mma<<<16, 256>>>(g1, b1);
    border_copy_kernel<<<dim3(129,2), 256>>>(1);

    // layer2: actB(raw, BN1 in-load) -> actA raw
    pack_g_kernel<<<1600, 256>>>(w2);
    mma_conv_kernel<<<1024, 128, SMEM>>>(1, 0);
    stats_final_mma<<<16, 256>>>(g2, b2);
    border_copy_kernel<<<dim3(129,2), 256>>>(0);

    // layer3: actA(raw, BN2 in-load) -> actB raw
    pack_g_kernel<<<1600, 256>>>(w3);
    mma_conv_kernel<<<1024, 128, SMEM>>>(0, 0);
    stats_final_mma<<<16, 256>>>(g3, b3);
    // no border copy: conv4 (1x1, kx=ky=2) reads interior only

    // conv4 (1x1): actB(raw, BN3 in-load) -> actA raw; BN4 folded into final
    pack_w4_kernel<<<64, 256>>>(w4);
    mma_conv_kernel<<<1024, 128, SMEM>>>(1, 1);
    stats_final_mma<<<16, 256>>>(g4, b4);

    final_kernel<<<512, 256>>>(fw, out);
}

// round 13
// speedup vs baseline: 1.2920x; 1.0070x over previous
#include <cuda_runtime.h>
#include <cuda_fp16.h>
#include <math.h>
#include <stdint.h>

#define HW 65536
#define PW 260

// ---------------- device scratch (allocation-free) ----------------
// Channel layout everywhere: q = o*16 + ci   (o = orientation, ci = base channel)
__device__ __align__(1024) __half g_actA[2*PW*PW*128];    // padded NHWC fp16 RAW (ping)
__device__ __align__(1024) __half g_actB[2*PW*PW*128];    // padded NHWC fp16 RAW (pong)
__device__ __align__(1024) __half g_wA[25*16384];         // gconv weights [tap][p][q] fp16
__device__ __align__(1024) __half g_wA4[16384];           // conv4 weights [p][q] fp16
__device__ __align__(1024) __half g_wL[7*4096];           // lift weights [ky][p][32] fp16
__device__ float g_ps1[1024*128], g_ps2[1024*128];        // stats partials
__device__ float g_sc[16], g_bi[16];

// ---------------- PTX helpers (sm_80-era, portable to plain sm_103) ----------------
__device__ __forceinline__ uint32_t smem_u32(const void* p) {
    uint32_t a;
    asm("{ .reg .u64 t; cvta.to.shared.u64 t, %1; cvt.u32.u64 %0, t; }" : "=r"(a) : "l"(p));
    return a;
}
__device__ __forceinline__ void cp_async16(uint32_t s, const void* g) {
    asm volatile("cp.async.cg.shared.global [%0], [%1], 16;" :: "r"(s), "l"(g) : "memory");
}
__device__ __forceinline__ void ldm_x4(uint32_t* r, uint32_t a) {
    asm volatile("ldmatrix.sync.aligned.m8n8.x4.shared.b16 {%0,%1,%2,%3}, [%4];"
        : "=r"(r[0]), "=r"(r[1]), "=r"(r[2]), "=r"(r[3]) : "r"(a));
}
__device__ __forceinline__ void mma16816(float* d, const uint32_t* a, const uint32_t* b) {
    asm volatile("mma.sync.aligned.m16n8k16.row.col.f32.f16.f16.f32 "
        "{%0,%1,%2,%3}, {%4,%5,%6,%7}, {%8,%9}, {%0,%1,%2,%3};"
        : "+f"(d[0]), "+f"(d[1]), "+f"(d[2]), "+f"(d[3])
        : "r"(a[0]), "r"(a[1]), "r"(a[2]), "r"(a[3]), "r"(b[0]), "r"(b[1]));
}
__device__ __forceinline__ void sts128(uint32_t a, uint4 v) {
    asm volatile("st.shared.v4.b32 [%0],{%1,%2,%3,%4};" :: "r"(a),"r"(v.x),"r"(v.y),"r"(v.z),"r"(v.w));
}

// ---------------- bilinear kernel rotation ----------------
__device__ __forceinline__ float rot_sample(const float* W, int k, float cs, float sn, int i, int j) {
    float c  = 0.5f * (float)(k - 1);
    float ys = (float)i - c, xs = (float)j - c;
    float sy = cs * ys - sn * xs + c;
    float sx = sn * ys + cs * xs + c;
    float fy = floorf(sy), fx = floorf(sx);
    int y0 = (int)fy, x0 = (int)fx;
    float wy = sy - fy, wx = sx - fx;
    float v00 = (y0   >= 0 && y0   < k && x0   >= 0 && x0   < k) ? W[y0*k + x0]       : 0.f;
    float v01 = (y0   >= 0 && y0   < k && x0+1 >= 0 && x0+1 < k) ? W[y0*k + x0 + 1]   : 0.f;
    float v10 = (y0+1 >= 0 && y0+1 < k && x0   >= 0 && x0   < k) ? W[(y0+1)*k + x0]   : 0.f;
    float v11 = (y0+1 >= 0 && y0+1 < k && x0+1 >= 0 && x0+1 < k) ? W[(y0+1)*k + x0+1] : 0.f;
    return v00*(1.f-wy)*(1.f-wx) + v01*(1.f-wy)*wx + v10*wy*(1.f-wx) + v11*wy*wx;
}

// pack lift weights: g_wL[ky][p=m*16+co][k=kx*3+ci (21 used, pad 32)]
__global__ void pack_lift_kernel(const float* __restrict__ lw) {
    int idx = blockIdx.x * 256 + threadIdx.x;   // 28672 = 112 blocks
    int ky = idx >> 12;
    int p  = (idx >> 5) & 127;
    int k  = idx & 31;
    int m = p >> 4, co = p & 15;
    float v = 0.f;
    if (k < 21) {
        int kx = k / 3, ci = k - kx*3;
        float th = (float)m * 0.78539816339744831f;
        v = rot_sample(lw + (co*3 + ci)*49, 7, cosf(th), sinf(th), ky, kx);
    }
    g_wL[idx] = __float2half(v);
}

// ---------------- fused inter-layer kernel: stats finalize + border copy + weight pack ----
// blocks [0,16): BN stats finalize for channel c=bx
// blocks [16,16+nb): border mirror copy (nb = 258 when border_which>=0, else 0)
// remaining blocks: weight pack (wmode 1 = gconv 5x5, wmode 2 = conv4 1x1)
__global__ void inter_kernel(const float* __restrict__ g, const float* __restrict__ b,
                             int border_which, const float* __restrict__ wsrc, int wmode) {
    int bx = blockIdx.x, t = threadIdx.x;
    if (bx < 16) {
        int c = bx;
        float s = 0.f, ss = 0.f;
        for (int e = t; e < 8192; e += 256) {
            int idx = (e >> 3) * 128 + ((e & 7) << 4) + c;
            s += g_ps1[idx]; ss += g_ps2[idx];
        }
        __shared__ float sh1[256], sh2[256];
        sh1[t] = s; sh2[t] = ss;
        __syncthreads();
        for (int off = 128; off > 0; off >>= 1) {
            if (t < off) { sh1[t] += sh1[t + off]; sh2[t] += sh2[t + off]; }
            __syncthreads();
        }
        if (t == 0) {
            const float invN = 1.0f / 1048576.0f;
            float mean = sh1[0] * invN;
            float var  = sh2[0] * invN - mean * mean;
            float sc = g[c] * rsqrtf(var + 1e-5f);
            g_sc[c] = sc;
            g_bi[c] = b[c] - mean * sc;
        }
        return;
    }
    int nb = (border_which >= 0) ? 258 : 0;
    if (bx < 16 + nb) {
        __half* act = border_which ? g_actB : g_actA;
        int idx = bx - 16;
        int bb = idx / 129, blk = idx - bb*129;
        int gid = blk*256 + t;
        if (gid >= 2064*16) return;
        int i = gid >> 4, qc = gid & 15;
        int py, px;
        if (i < 520)       { py = i / 260;                 px = i % 260; }
        else if (i < 1040) { int j = i - 520; py = 258 + j / 260; px = j % 260; }
        else               { int j = i - 1040; py = 2 + (j >> 2); int c = j & 3; px = (c & 1) + ((c >> 1) * 258); }
        int uy = py - 2; uy = uy < 0 ? -uy : (uy > 255 ? 510 - uy : uy);
        int ux = px - 2; ux = ux < 0 ? -ux : (ux > 255 ? 510 - ux : ux);
        uint4 v = *(uint4*)(act + ((size_t)(bb*PW + uy + 2)*PW + ux + 2)*128 + qc*8);
        *(uint4*)(act + ((size_t)(bb*PW + py)*PW + px)*128 + qc*8) = v;
        return;
    }
    int pidx = (bx - 16 - nb)*256 + t;
    if (wmode == 1) {
        // pack gconv weights: A[tap][p=m*16+co][q=o*16+ci], 409600 items (1600 blocks)
        int tap = pidx >> 14;
        int p = (pidx >> 7) & 127, q = pidx & 127;
        int m = p >> 4, co = p & 15, o = q >> 4, ci = q & 15;
        int oo = (o - m) & 7;
        float th = (float)m * 0.78539816339744831f;
        float cs = cosf(th), sn = sinf(th);
        float v = rot_sample(wsrc + ((co*16 + ci)*8 + oo)*25, 5, cs, sn, tap/5, tap%5);
        g_wA[tap*16384 + p*128 + q] = __float2half(v);
    } else if (wmode == 2) {
        // pack conv4 weights: 16384 items (64 blocks)
        int p = pidx >> 7, q = pidx & 127;
        int m = p >> 4, co = p & 15, o = q >> 4, ci = q & 15;
        g_wA4[pidx] = __float2half(wsrc[(co*16 + ci)*8 + ((o - m) & 7)]);
    }
}

// ---------------- lift as HMMA implicit GEMM ----------------
__global__ __launch_bounds__(256, 2) void lift_mma_kernel(const float* __restrict__ x) {
    extern __shared__ __align__(256) char dsm[];
    uint32_t sbase = smem_u32(dsm);
    uint32_t Wb = sbase + 16384;
    float* s_raw = (float*)(dsm + 49152);
    float* s_sum = (float*)(dsm + 51200);
    float* s_sq  = (float*)(dsm + 52224);

    int tid = threadIdx.x, w = tid >> 5, lane = tid & 31;
    int mw = w & 3, nw = w >> 2;
    int tile = blockIdx.x;
    int b = tile >> 9, rem = tile & 511;
    int y = rem >> 1, xh = (rem & 1) << 7;

    float d[2][8][4];
#pragma unroll
    for (int mi = 0; mi < 2; ++mi)
#pragma unroll
        for (int nn = 0; nn < 8; ++nn)
#pragma unroll
            for (int k = 0; k < 4; ++k) d[mi][nn][k] = 0.f;

    auto load_w = [&](int ky, int stg) {
        const __half* src = g_wL + ky * 4096;
        uint32_t Ab = Wb + (uint32_t)stg * 16384;
#pragma unroll
        for (int i = 0; i < 2; ++i) {
            int id = i*256 + tid;
            int r = id >> 2, c = id & 3;
            cp_async16(Ab + r*128 + ((c ^ (r & 7)) * 16), src + id*8);
        }
    };

    load_w(0, 0);
    asm volatile("cp.async.commit_group;" ::: "memory");

#pragma unroll 1
    for (int ky = 0; ky < 7; ++ky) {
        int yy = y + ky - 3; yy = yy < 0 ? -yy : (yy > 255 ? 510 - yy : yy);
        for (int id = tid; id < 402; id += 256) {
            int ci = id / 134, ix = id - ci*134;
            int gx = xh + ix - 3; gx = gx < 0 ? -gx : (gx > 255 ? 510 - gx : gx);
            s_raw[id] = x[(b*3 + ci)*HW + yy*256 + gx];
        }
        if (ky + 1 < 7) {
            load_w(ky + 1, (ky + 1) & 1);
            asm volatile("cp.async.commit_group;" ::: "memory");
            asm volatile("cp.async.wait_group 1;" ::: "memory");
        } else {
            asm volatile("cp.async.wait_group 0;" ::: "memory");
        }
        __syncthreads();
#pragma unroll
        for (int i = 0; i < 2; ++i) {
            int cid = i*256 + tid;
            int px = cid >> 2, c = cid & 3;
            __half vals[8];
#pragma unroll
            for (int j = 0; j < 8; ++j) {
                int k = c*8 + j;
                float f = 0.f;
                if (k < 21) { int kx = k/3; int ci = k - kx*3; f = s_raw[ci*134 + px + kx]; }
                vals[j] = __float2half(f);
            }
            sts128(sbase + px*128 + ((c ^ (px & 7)) * 16), *(uint4*)vals);
        }
        __syncthreads();
        uint32_t Ab = Wb + (uint32_t)(ky & 1) * 16384;
        int arb = mw*32 + (lane & 15);
        int acs = lane >> 4;
        int brb = nw*64 + (lane & 7) + ((lane >> 4) << 3);
        int bcs = (lane >> 3) & 1;
#pragma unroll
        for (int ks = 0; ks < 2; ++ks) {
            uint32_t a[2][4];
#pragma unroll
            for (int mi = 0; mi < 2; ++mi) {
                int r = arb + mi*16, c = ks*2 + acs;
                ldm_x4(a[mi], Ab + r*128 + ((c ^ (r & 7)) * 16));
            }
            uint32_t bf[8][2];
#pragma unroll
            for (int nj = 0; nj < 4; ++nj) {
                int r = brb + nj*16, c = ks*2 + bcs;
                uint32_t q[4];
                ldm_x4(q, sbase + r*128 + ((c ^ (r & 7)) * 16));
                bf[nj*2][0] = q[0]; bf[nj*2][1] = q[1];
                bf[nj*2+1][0] = q[2]; bf[nj*2+1][1] = q[3];
            }
#pragma unroll
            for (int mi = 0; mi < 2; ++mi)
#pragma unroll
                for (int nn = 0; nn < 8; ++nn)
                    mma16816(d[mi][nn], a[mi], bf[nn]);
        }
        __syncthreads();
    }

    int g = lane >> 2, q4 = lane & 3;
    float psum[4], psq[4];
#pragma unroll
    for (int i = 0; i < 4; ++i) { psum[i] = 0.f; psq[i] = 0.f; }
#pragma unroll
    for (int mi = 0; mi < 2; ++mi)
#pragma unroll
        for (int hh = 0; hh < 2; ++hh) {
            int pidx = mi*2 + hh;
#pragma unroll
            for (int nn = 0; nn < 8; ++nn) {
                float v0 = d[mi][nn][hh*2 + 0], v1 = d[mi][nn][hh*2 + 1];
                psum[pidx] += v0 + v1;
                psq[pidx]  += v0*v0 + v1*v1;
            }
        }
#pragma unroll
    for (int i = 0; i < 4; ++i) {
        psum[i] += __shfl_xor_sync(0xFFFFFFFF, psum[i], 1);
        psum[i] += __shfl_xor_sync(0xFFFFFFFF, psum[i], 2);
        psq[i]  += __shfl_xor_sync(0xFFFFFFFF, psq[i], 1);
        psq[i]  += __shfl_xor_sync(0xFFFFFFFF, psq[i], 2);
    }
    if (q4 == 0) {
#pragma unroll
        for (int mi = 0; mi < 2; ++mi)
#pragma unroll
            for (int hh = 0; hh < 2; ++hh) {
                int p = mw*32 + mi*16 + hh*8 + g;
                s_sum[nw*128 + p] = psum[mi*2 + hh];
                s_sq[nw*128 + p]  = psq[mi*2 + hh];
            }
    }
    __half* s_out = (__half*)dsm;
#pragma unroll
    for (int mi = 0; mi < 2; ++mi)
#pragma unroll
        for (int hh = 0; hh < 2; ++hh) {
            int p = mw*32 + mi*16 + hh*8 + g;
#pragma unroll
            for (int nn = 0; nn < 8; ++nn) {
                int px = nw*64 + nn*8 + q4*2;
                s_out[(size_t)px*136 + p]     = __float2half(d[mi][nn][hh*2 + 0]);
                s_out[(size_t)(px+1)*136 + p] = __float2half(d[mi][nn][hh*2 + 1]);
            }
        }
    __syncthreads();
    if (tid < 128) {
        g_ps1[tile*128 + tid] = s_sum[tid] + s_sum[128 + tid];
        g_ps2[tile*128 + tid] = s_sq[tid]  + s_sq[128 + tid];
    }
    __half* ob = g_actA + ((size_t)(b*PW + y + 2)*PW + 2 + xh)*128;
    for (int id = tid; id < 2048; id += 256) {
        int px = id >> 4, qc = id & 15;
        *(uint4*)(ob + (size_t)px*128 + qc*8) = *(uint4*)((char*)dsm + px*272 + qc*16);
    }
}

// ---------------- mma.sync implicit-GEMM conv: 4 warps x 64p x 64px, occ 2 ----------------
#define BSTG 33792   // 132 px x 256 B
__global__ __launch_bounds__(128, 2) void mma_conv_kernel(int dir, int is1x1) {
    extern __shared__ __align__(256) char dsm[];
    uint32_t sbase = smem_u32(dsm);
    uint32_t Wbase = sbase + BSTG;
    float* s_sum = (float*)(dsm + BSTG + 65536);   // [2][128]
    float* s_sq  = (float*)(dsm + BSTG + 65536 + 1024);
    __shared__ float s_sc[16], s_bi[16];

    const __half* actin = dir ? g_actB : g_actA;
    __half* actout      = dir ? g_actA : g_actB;

    int tid = threadIdx.x, w = tid >> 5, lane = tid & 31;
    int mw = w & 1, nw = w >> 1;
    int tile = blockIdx.x;
    int b = tile >> 9, rem = tile & 511;
    int y = rem >> 1, xh = (rem & 1) << 7;
    int ntap = is1x1 ? 1 : 25;
    const __half* wsrc = is1x1 ? g_wA4 : g_wA;
    const __half* actb = actin + (size_t)b * PW * PW * 128;

    if (tid < 16) { s_sc[tid] = g_sc[tid]; s_bi[tid] = g_bi[tid]; }

    float d[4][8][4];
#pragma unroll
    for (int mi = 0; mi < 4; ++mi)
#pragma unroll
        for (int nn = 0; nn < 8; ++nn)
#pragma unroll
            for (int k = 0; k < 4; ++k) d[mi][nn][k] = 0.f;

    auto load_brow = [&](int ky) {
        const __half* src = actb + ((size_t)(y + ky) * PW + xh) * 128;
        for (int id = tid; id < 2112; id += 128) {
            int r = id >> 4, c = id & 15;
            cp_async16(sbase + r*256 + ((c ^ (r & 7)) * 16), src + id*8);
        }
    };
    auto load_w = [&](int tp, int stg) {
        const __half* src = wsrc + tp * 16384;
        uint32_t Ab = Wbase + (uint32_t)stg * 32768;
#pragma unroll
        for (int it = 0; it < 16; ++it) {
            int id = it*128 + tid; int r = id >> 4, c = id & 15;
            cp_async16(Ab + r*256 + ((c ^ (r & 7)) * 16), src + id*8);
        }
    };
    auto bn_stage = [&]() {
        for (int id = tid; id < 2112; id += 128) {
            int r = id >> 4, c = id & 15;
            uint32_t ad = sbase + r*256 + ((c ^ (r & 7)) * 16);
            uint4 v; asm volatile("ld.shared.v4.b32 {%0,%1,%2,%3}, [%4];"
                : "=r"(v.x), "=r"(v.y), "=r"(v.z), "=r"(v.w) : "r"(ad));
            __half* h = (__half*)&v;
            int cbase = (c & 1) << 3;
#pragma unroll
            for (int k = 0; k < 8; ++k)
                h[k] = __float2half(fmaxf(fmaf(__half2float(h[k]), s_sc[cbase + k], s_bi[cbase + k]), 0.f));
            asm volatile("st.shared.v4.b32 [%0], {%1,%2,%3,%4};"
                :: "r"(ad), "r"(v.x), "r"(v.y), "r"(v.z), "r"(v.w));
        }
    };

    load_brow(is1x1 ? 2 : 0);
    load_w(0, 0);
    asm volatile("cp.async.commit_group;" ::: "memory");

#pragma unroll 1
    for (int t = 0; t < ntap; ++t) {
        int kx = is1x1 ? 2 : t % 5;
        if (t + 1 < ntap) {
            load_w(t + 1, (t + 1) & 1);
            asm volatile("cp.async.commit_group;" ::: "memory");
            asm volatile("cp.async.wait_group 1;" ::: "memory");
        } else {
            asm volatile("cp.async.wait_group 0;" ::: "memory");
        }
        __syncthreads();
        if ((t % 5) == 0) {
            bn_stage();
            __syncthreads();
        }
        uint32_t Ab = Wbase + (uint32_t)(t & 1) * 32768;
        int arb = mw*64 + (lane & 15);
        int acs = lane >> 4;
        int brb = kx + nw*64 + (lane & 7) + ((lane >> 4) << 3);
        int bcs = (lane >> 3) & 1;
#pragma unroll
        for (int ks = 0; ks < 8; ++ks) {
            uint32_t a[4][4];
#pragma unroll
            for (int mi = 0; mi < 4; ++mi) {
                int r = arb + mi*16, c = ks*2 + acs;
                ldm_x4(a[mi], Ab + r*256 + ((c ^ (r & 7)) * 16));
            }
            uint32_t bf[8][2];
#pragma unroll
            for (int nj = 0; nj < 4; ++nj) {
                int r = brb + nj*16, c = ks*2 + bcs;
                uint32_t q[4];
                ldm_x4(q, sbase + r*256 + ((c ^ (r & 7)) * 16));
                bf[nj*2][0] = q[0]; bf[nj*2][1] = q[1];
                bf[nj*2+1][0] = q[2]; bf[nj*2+1][1] = q[3];
            }
#pragma unroll
            for (int mi = 0; mi < 4; ++mi)
#pragma unroll
                for (int nn = 0; nn < 8; ++nn)
                    mma16816(d[mi][nn], a[mi], bf[nn]);
        }
        __syncthreads();
        if (!is1x1 && (t + 1) % 5 == 0 && t + 1 < ntap) {
            load_brow((t + 1) / 5);
            asm volatile("cp.async.commit_group;" ::: "memory");
        }
    }

    // ---- deterministic per-p sums ----
    int g = lane >> 2, q4 = lane & 3;
    float psum[8], psq[8];
#pragma unroll
    for (int i = 0; i < 8; ++i) { psum[i] = 0.f; psq[i] = 0.f; }
#pragma unroll
    for (int mi = 0; mi < 4; ++mi)
#pragma unroll
        for (int hh = 0; hh < 2; ++hh) {
            int pidx = mi*2 + hh;
#pragma unroll
            for (int nn = 0; nn < 8; ++nn) {
                float v0 = d[mi][nn][hh*2 + 0], v1 = d[mi][nn][hh*2 + 1];
                psum[pidx] += v0 + v1;
                psq[pidx]  += v0*v0 + v1*v1;
            }
        }
#pragma unroll
    for (int i = 0; i < 8; ++i) {
        psum[i] += __shfl_xor_sync(0xFFFFFFFF, psum[i], 1);
        psum[i] += __shfl_xor_sync(0xFFFFFFFF, psum[i], 2);
        psq[i]  += __shfl_xor_sync(0xFFFFFFFF, psq[i], 1);
        psq[i]  += __shfl_xor_sync(0xFFFFFFFF, psq[i], 2);
    }
    if (q4 == 0) {
#pragma unroll
        for (int mi = 0; mi < 4; ++mi)
#pragma unroll
            for (int hh = 0; hh < 2; ++hh) {
                int p = mw*64 + mi*16 + hh*8 + g;
                s_sum[nw*128 + p] = psum[mi*2 + hh];
                s_sq[nw*128 + p]  = psq[mi*2 + hh];
            }
    }
    // ---- transpose D -> raw fp16 NHWC via smem (reuse B + W0 area) ----
    __half* s_out = (__half*)dsm;
#pragma unroll
    for (int mi = 0; mi < 4; ++mi)
#pragma unroll
        for (int hh = 0; hh < 2; ++hh) {
            int p = mw*64 + mi*16 + hh*8 + g;
#pragma unroll
            for (int nn = 0; nn < 8; ++nn) {
                int px = nw*64 + nn*8 + q4*2;
                s_out[(size_t)px*136 + p]     = __float2half(d[mi][nn][hh*2 + 0]);
                s_out[(size_t)(px+1)*136 + p] = __float2half(d[mi][nn][hh*2 + 1]);
            }
        }
    __syncthreads();
    g_ps1[tile*128 + tid] = s_sum[tid] + s_sum[128 + tid];
    g_ps2[tile*128 + tid] = s_sq[tid]  + s_sq[128 + tid];
    __half* ob = actout + ((size_t)(b*PW + y + 2)*PW + 2 + xh)*128;
    for (int id = tid; id < 2048; id += 128) {
        int px = id >> 4, qc = id & 15;
        *(uint4*)(ob + (size_t)px*128 + qc*8) = *(uint4*)((char*)dsm + px*272 + qc*16);
    }
}

// ---------------- final: BN4+ReLU, max over m, 1x1 + sigmoid (conv4 raw fp16 in actA) ----------------
__global__ void final_kernel(const float* __restrict__ fw, float* __restrict__ out) {
    int gid = blockIdx.x * 256 + threadIdx.x;    // 131072
    int b = gid >> 16, pix = gid & 65535;
    int y = pix >> 8, x = pix & 255;
    const __half* p = g_actA + ((size_t)(b*PW + y + 2)*PW + x + 2)*128;
    float sc[16], bi[16], mv[16];
#pragma unroll
    for (int ci = 0; ci < 16; ++ci) { sc[ci] = g_sc[ci]; bi[ci] = g_bi[ci]; mv[ci] = 0.f; }
#pragma unroll 1
    for (int m = 0; m < 8; ++m) {
        uint4 v0 = *(const uint4*)(p + m*16);
        uint4 v1 = *(const uint4*)(p + m*16 + 8);
        const __half* h0 = (const __half*)&v0;
        const __half* h1 = (const __half*)&v1;
#pragma unroll
        for (int k = 0; k < 8; ++k) {
            mv[k]     = fmaxf(mv[k],     fmaf(__half2float(h0[k]), sc[k],     bi[k]));
            mv[8 + k] = fmaxf(mv[8 + k], fmaf(__half2float(h1[k]), sc[8 + k], bi[8 + k]));
        }
    }
    float acc = 0.f;
#pragma unroll
    for (int ci = 0; ci < 16; ++ci) acc = fmaf(fw[ci], mv[ci], acc);
    out[gid] = 1.0f / (1.0f + expf(-acc));
}

// ---------------- launch ----------------
extern "C" void kernel_launch(void* const* d_in, const int* in_sizes, int n_in,
                              void* d_out, int out_size) {
    const float* x  = (const float*)d_in[0];
    const float* lw = (const float*)d_in[1];
    const float* w1 = (const float*)d_in[2];
    const float* w2 = (const float*)d_in[3];
    const float* w3 = (const float*)d_in[4];
    const float* w4 = (const float*)d_in[5];
    const float* fw = (const float*)d_in[6];
    const float* g0 = (const float*)d_in[7];  const float* b0 = (const float*)d_in[8];
    const float* g1 = (const float*)d_in[9];  const float* b1 = (const float*)d_in[10];
    const float* g2 = (const float*)d_in[11]; const float* b2 = (const float*)d_in[12];
    const float* g3 = (const float*)d_in[13]; const float* b3 = (const float*)d_in[14];
    const float* g4 = (const float*)d_in[15]; const float* b4 = (const float*)d_in[16];
    float* out = (float*)d_out;

    const int SMEM  = 101376;   // gconv: B window 33792 + 2 W stages 65536 + sums 2048
    const int SMEML = 53248;    // lift:  B 16384 + 2 W 32768 + raw 2048 + sums 2048
    cudaFuncSetAttribute(mma_conv_kernel, cudaFuncAttributeMaxDynamicSharedMemorySize, SMEM);
    cudaFuncSetAttribute(lift_mma_kernel, cudaFuncAttributeMaxDynamicSharedMemorySize, SMEML);

    // lift (HMMA) -> raw fp16 actA interior + BN0 partials
    pack_lift_kernel<<<112, 256>>>(lw);
    lift_mma_kernel<<<1024, 256, SMEML>>>(x);

    // inter1: BN0 stats + border(A) + pack w1
    inter_kernel<<<16 + 258 + 1600, 256>>>(g0, b0, 0, w1, 1);
    mma_conv_kernel<<<1024, 128, SMEM>>>(0, 0);          // A -> B

    // inter2: BN1 stats + border(B) + pack w2
    inter_kernel<<<16 + 258 + 1600, 256>>>(g1, b1, 1, w2, 1);
    mma_conv_kernel<<<1024, 128, SMEM>>>(1, 0);          // B -> A

    // inter3: BN2 stats + border(A) + pack w3
    inter_kernel<<<16 + 258 + 1600, 256>>>(g2, b2, 0, w3, 1);
    mma_conv_kernel<<<1024, 128, SMEM>>>(0, 0);          // A -> B

    // inter4: BN3 stats + pack w4 (no border: conv4 reads interior only)
    inter_kernel<<<16 + 64, 256>>>(g3, b3, -1, w4, 2);
    mma_conv_kernel<<<1024, 128, SMEM>>>(1, 1);          // B -> A (1x1)

    // inter5: BN4 stats only
    inter_kernel<<<16, 256>>>(g4, b4, -1, (const float*)0, 0);
    final_kernel<<<512, 256>>>(fw, out);
}